// round 6
// baseline (speedup 1.0000x reference)
#include <cuda_runtime.h>
#include <cuda_bf16.h>
#include <cstdint>

// ============================================================================
// GridNeRF forward: register-chained mma.sync.m16n8k16 (bf16 hi/lo => ~fp32).
// M=32 per warp (two 16-row tiles share every B ldmatrix).
//   L1: A1[16,48] @ W1t -> 8 n8 (bias folded: col47=1)
//   L2: H1[16,64] @ W2t -> 9 n8 (cols0..63 feat, col64 sigma)
//   L3: A3[16,80] @ W3t -> 8 n8 (A3 = feat ++ SH ++ 1 ++ 0, bias row73)
//   L4: H3[16,64] @ W4t -> 1 n8 (cols0..2 -> sigmoid rgb)
// 3 MMA passes per k-tile: Ah*Bh + Al*Bh + Ah*Bl.
// ============================================================================

constexpr int TSZ = 1 << 19;

constexpr int sW1 = 56, sW2 = 72, sW3 = 88, sW4 = 72;   // elem strides [N][K]
constexpr int oW1h = 0;
constexpr int oW1l = oW1h + 64 * sW1;
constexpr int oW2h = oW1l + 64 * sW1;
constexpr int oW2l = oW2h + 72 * sW2;
constexpr int oW3h = oW2l + 72 * sW2;
constexpr int oW3l = oW3h + 64 * sW3;
constexpr int oW4h = oW3l + 64 * sW3;
constexpr int oW4l = oW4h + 8 * sW4;
constexpr int W_ELEMS = oW4l + 8 * sW4;                 // 29952 elems

__device__ __align__(16) __nv_bfloat16 g_w[W_ELEMS];
__device__ __align__(16) float g_b2[72];
__device__ __align__(16) float g_b4[8];

constexpr int oSB2B = 59904;
constexpr int oSB4B = 60192;
constexpr int oSTB  = 60224;                 // per warp: 2 tiles x (2304 hi + 2304 lo)
constexpr int SMEM_DYN = oSTB + 8 * 9216;    // 133952

// ---------------- PTX helpers ----------------
__device__ __forceinline__ uint32_t smem_u32(const void* p) {
    uint32_t a;
    asm("{ .reg .u64 t; cvta.to.shared.u64 t, %1; cvt.u32.u64 %0, t; }"
        : "=r"(a) : "l"(p));
    return a;
}
__device__ __forceinline__ void ldsm4(uint32_t* r, uint32_t addr) {
    asm volatile("ldmatrix.sync.aligned.m8n8.x4.shared.b16 {%0,%1,%2,%3}, [%4];"
        : "=r"(r[0]), "=r"(r[1]), "=r"(r[2]), "=r"(r[3]) : "r"(addr));
}
__device__ __forceinline__ void ldsm2(uint32_t& r0, uint32_t& r1, uint32_t addr) {
    asm volatile("ldmatrix.sync.aligned.m8n8.x2.shared.b16 {%0,%1}, [%2];"
        : "=r"(r0), "=r"(r1) : "r"(addr));
}
#define MMA4(c, a, b0_, b1_) \
    asm volatile("mma.sync.aligned.m16n8k16.row.col.f32.bf16.bf16.f32 " \
        "{%0,%1,%2,%3},{%4,%5,%6,%7},{%8,%9},{%0,%1,%2,%3};" \
        : "+f"((c)[0]), "+f"((c)[1]), "+f"((c)[2]), "+f"((c)[3]) \
        : "r"((a)[0]), "r"((a)[1]), "r"((a)[2]), "r"((a)[3]), "r"(b0_), "r"(b1_))

// 2 k-tiles, 2 row-tiles: Bh ldsm4 shared by 8 MMA, Bl by 4
__device__ __forceinline__ void pass2d(float* c0, float* c1,
    const uint32_t (*ah0)[4], const uint32_t (*al0)[4],
    const uint32_t (*ah1)[4], const uint32_t (*al1)[4], int k0,
    uint32_t bh_addr, uint32_t bl_addr)
{
    uint32_t bb[4];
    ldsm4(bb, bh_addr);
    MMA4(c0, ah0[k0], bb[0], bb[1]);
    MMA4(c1, ah1[k0], bb[0], bb[1]);
    MMA4(c0, ah0[k0 + 1], bb[2], bb[3]);
    MMA4(c1, ah1[k0 + 1], bb[2], bb[3]);
    MMA4(c0, al0[k0], bb[0], bb[1]);
    MMA4(c1, al1[k0], bb[0], bb[1]);
    MMA4(c0, al0[k0 + 1], bb[2], bb[3]);
    MMA4(c1, al1[k0 + 1], bb[2], bb[3]);
    ldsm4(bb, bl_addr);
    MMA4(c0, ah0[k0], bb[0], bb[1]);
    MMA4(c1, ah1[k0], bb[0], bb[1]);
    MMA4(c0, ah0[k0 + 1], bb[2], bb[3]);
    MMA4(c1, ah1[k0 + 1], bb[2], bb[3]);
}
__device__ __forceinline__ void pass1d(float* c0, float* c1,
    const uint32_t* ah0, const uint32_t* al0,
    const uint32_t* ah1, const uint32_t* al1,
    uint32_t bh_addr, uint32_t bl_addr)
{
    uint32_t r0, r1;
    ldsm2(r0, r1, bh_addr);
    MMA4(c0, ah0, r0, r1);
    MMA4(c1, ah1, r0, r1);
    MMA4(c0, al0, r0, r1);
    MMA4(c1, al1, r0, r1);
    ldsm2(r0, r1, bl_addr);
    MMA4(c0, ah0, r0, r1);
    MMA4(c1, ah1, r0, r1);
}

__device__ __forceinline__ uint32_t bf2r(float a, float b, uint32_t& lo) {
    a = fmaxf(a, 0.0f); b = fmaxf(b, 0.0f);
    __nv_bfloat162 h = __floats2bfloat162_rn(a, b);
    __nv_bfloat162 l = __floats2bfloat162_rn(a - __bfloat162float(h.x),
                                             b - __bfloat162float(h.y));
    lo = *reinterpret_cast<uint32_t*>(&l);
    return *reinterpret_cast<uint32_t*>(&h);
}

// ---------------- weight prep ----------------
__device__ __forceinline__ void put_w(int hi, int lo, float w) {
    __nv_bfloat16 h = __float2bfloat16(w);
    g_w[hi] = h;
    g_w[lo] = __float2bfloat16(w - __bfloat162float(h));
}

__global__ void prep_weights(const float* __restrict__ dw1, const float* __restrict__ db1,
                             const float* __restrict__ dw2, const float* __restrict__ db2,
                             const float* __restrict__ rw1, const float* __restrict__ rb1,
                             const float* __restrict__ rw2, const float* __restrict__ rb2)
{
    const int tid = threadIdx.x;
    for (int i = tid; i < W_ELEMS; i += 256) g_w[i] = __float2bfloat16(0.0f);
    __syncthreads();
    for (int i = tid; i < 64 * 48; i += 256) {
        int nn = i / 48, k = i % 48;
        float w = (k < 47) ? dw1[k * 64 + nn] : db1[nn];
        put_w(oW1h + nn * sW1 + k, oW1l + nn * sW1 + k, w);
    }
    for (int i = tid; i < 65 * 64; i += 256) {
        int nn = i / 64, k = i % 64;
        float w = (nn < 64) ? dw2[k * 65 + nn + 1] : dw2[k * 65];
        put_w(oW2h + nn * sW2 + k, oW2l + nn * sW2 + k, w);
    }
    for (int i = tid; i < 64 * 74; i += 256) {
        int nn = i / 74, k = i % 74;
        float w = (k < 73) ? rw1[k * 64 + nn] : rb1[nn];
        put_w(oW3h + nn * sW3 + k, oW3l + nn * sW3 + k, w);
    }
    for (int i = tid; i < 3 * 64; i += 256) {
        int nn = i / 64, k = i % 64;
        put_w(oW4h + nn * sW4 + k, oW4l + nn * sW4 + k, rw2[k * 3 + nn]);
    }
    if (tid < 72) g_b2[tid] = (tid < 64) ? db2[tid + 1] : ((tid == 64) ? db2[0] : 0.0f);
    if (tid < 8)  g_b4[tid] = (tid < 3) ? rb2[tid] : 0.0f;
}

// ---------------- encoding ----------------
__device__ __forceinline__ void put_st(__nv_bfloat16* H, __nv_bfloat16* L,
                                       int r, int c, float w) {
    __nv_bfloat16 h = __float2bfloat16(w);
    H[r * 72 + c] = h;
    L[r * 72 + c] = __float2bfloat16(w - __bfloat162float(h));
}

__device__ __forceinline__ void encode_tile(
    __nv_bfloat16* stH, __nv_bfloat16* stL, int row, int half, int p,
    const float* __restrict__ x, const float* __restrict__ v,
    const float* __restrict__ table)
{
    const float px0 = x[3 * p], px1 = x[3 * p + 1], px2 = x[3 * p + 2];
    if (half == 0) {
        put_st(stH, stL, row, 0, px0);
        put_st(stH, stL, row, 1, px1);
        put_st(stH, stL, row, 2, px2);
        const float pv[2] = {px0, px1};
        #pragma unroll
        for (int d = 0; d < 2; d++) {
            float fm = 1.0f;
            #pragma unroll
            for (int fr = 0; fr < 6; fr++) {
                float s, c;
                __sincosf(pv[d] * fm, &s, &c);
                put_st(stH, stL, row, 3 + d * 12 + fr, s);
                put_st(stH, stL, row, 3 + d * 12 + 6 + fr, c);
                fm *= 2.0f;
            }
        }
        const float vx = v[3 * p], vy = v[3 * p + 1], vz = v[3 * p + 2];
        put_st(stH, stL, row, 48, 0.28209479177387814f);
        put_st(stH, stL, row, 49, -0.4886025119029199f * vy);
        put_st(stH, stL, row, 50,  0.4886025119029199f * vz);
        put_st(stH, stL, row, 51, -0.4886025119029199f * vx);
        put_st(stH, stL, row, 52,  1.0925484305920792f * vx * vy);
        put_st(stH, stL, row, 53, -1.0925484305920792f * vy * vz);
        put_st(stH, stL, row, 54,  0.9461746957575601f * vz * vz - 0.31539156525252005f);
        put_st(stH, stL, row, 55, -1.0925484305920792f * vx * vz);
        put_st(stH, stL, row, 56,  0.5462742152960396f * (vx * vx - vy * vy));
        put_st(stH, stL, row, 57, 1.0f);
        #pragma unroll
        for (int q = 58; q < 64; q++) put_st(stH, stL, row, q, 0.0f);
    } else {
        float fm = 1.0f;
        #pragma unroll
        for (int fr = 0; fr < 6; fr++) {
            float s, c;
            __sincosf(px2 * fm, &s, &c);
            put_st(stH, stL, row, 27 + fr, s);
            put_st(stH, stL, row, 33 + fr, c);
            fm *= 2.0f;
        }
        const float x01x = (px0 + 1.0f) * 0.5f;
        const float x01y = (px1 + 1.0f) * 0.5f;
        const float x01z = (px2 + 1.0f) * 0.5f;
        const float resf[4] = {33.0f, 43.0f, 56.0f, 74.0f};
        #pragma unroll
        for (int lv = 0; lv < 4; lv++) {
            const float pxx = x01x * resf[lv], pyy = x01y * resf[lv], pzz = x01z * resf[lv];
            const float fx = floorf(pxx), fy = floorf(pyy), fz = floorf(pzz);
            const float tx = pxx - fx, ty = pyy - fy, tz = pzz - fz;
            const float wx = tx * tx * (3.0f - 2.0f * tx);
            const float wy = ty * ty * (3.0f - 2.0f * ty);
            const float wz = tz * tz * (3.0f - 2.0f * tz);
            const unsigned cx = (unsigned)fx, cy = (unsigned)fy, cz = (unsigned)fz;
            const float* tb = table + (size_t)lv * (TSZ * 2);
            float f0 = 0.0f, f1 = 0.0f;
            #pragma unroll
            for (int c = 0; c < 8; c++) {
                const unsigned hx = cx + (c & 1);
                const unsigned hy = cy + ((c >> 1) & 1);
                const unsigned hz = cz + ((c >> 2) & 1);
                const unsigned hsh = (hx ^ (hy * 2654435761u) ^ (hz * 805459861u)) & (unsigned)(TSZ - 1);
                const float cw = ((c & 1) ? wx : 1.0f - wx)
                               * (((c >> 1) & 1) ? wy : 1.0f - wy)
                               * (((c >> 2) & 1) ? wz : 1.0f - wz);
                const float2 tv = __ldg(reinterpret_cast<const float2*>(tb + 2u * hsh));
                f0 = fmaf(tv.x, cw, f0);
                f1 = fmaf(tv.y, cw, f1);
            }
            put_st(stH, stL, row, 39 + 2 * lv, f0);
            put_st(stH, stL, row, 40 + 2 * lv, f1);
        }
        put_st(stH, stL, row, 47, 1.0f);
    }
}

__device__ __forceinline__ float sigmoidf_(float z) {
    return 1.0f / (1.0f + __expf(-z));
}

// ---------------- main kernel ----------------
__global__ void __launch_bounds__(256) nerf_mma3(
    const float* __restrict__ x, const float* __restrict__ v,
    const float* __restrict__ table, float* __restrict__ out, int n)
{
    extern __shared__ __align__(16) unsigned char S[];
    const int tid = threadIdx.x, wid = tid >> 5, lane = tid & 31;

    for (int i = tid; i < 59904 / 16; i += 256)
        ((uint4*)S)[i] = ((const uint4*)g_w)[i];
    float* sB2 = (float*)(S + oSB2B);
    float* sB4 = (float*)(S + oSB4B);
    if (tid < 72) sB2[tid] = g_b2[tid];
    if (tid < 8)  sB4[tid] = g_b4[tid];
    __syncthreads();

    const uint32_t uS = smem_u32(S);
    const int g = lane >> 2, t2 = (lane & 3) * 2;
    const int row = lane >> 1, half = lane & 1;

    __nv_bfloat16* st0H = (__nv_bfloat16*)(S + oSTB + wid * 9216);
    __nv_bfloat16* st0L = st0H + 1152;
    __nv_bfloat16* st1H = st0H + 2304;
    __nv_bfloat16* st1L = st0H + 3456;
    const uint32_t uSt0H = uS + oSTB + wid * 9216;
    const uint32_t uSt0L = uSt0H + 2304;
    const uint32_t uSt1H = uSt0H + 4608;
    const uint32_t uSt1L = uSt0H + 6912;

    const uint32_t aofs   = (lane & 15) * 144 + (lane >> 4) * 16;
    const uint32_t bo112  = (lane & 7) * 112 + (lane >> 3) * 16;
    const uint32_t bo112b = (lane & 7) * 112 + ((lane >> 3) & 1) * 16;
    const uint32_t bo144  = (lane & 7) * 144 + (lane >> 3) * 16;
    const uint32_t bo176  = (lane & 7) * 176 + (lane >> 3) * 16;
    const uint32_t bo176b = (lane & 7) * 176 + ((lane >> 3) & 1) * 16;

    const uint32_t uW1h  = uS + oW1h * 2 + bo112,        uW1l  = uS + oW1l * 2 + bo112;
    const uint32_t uW1hb = uS + oW1h * 2 + 64 + bo112b,  uW1lb = uS + oW1l * 2 + 64 + bo112b;
    const uint32_t uW2h  = uS + oW2h * 2 + bo144,        uW2l  = uS + oW2l * 2 + bo144;
    const uint32_t uW3h  = uS + oW3h * 2 + bo176,        uW3l  = uS + oW3l * 2 + bo176;
    const uint32_t uW3hb = uS + oW3h * 2 + 128 + bo176b, uW3lb = uS + oW3l * 2 + 128 + bo176b;
    const uint32_t uW4h  = uS + oW4h * 2 + bo144,        uW4l  = uS + oW4l * 2 + bo144;

    const int npairs = n >> 5;
    const int totw = gridDim.x * 8;

    for (int pair = blockIdx.x * 8 + wid; pair < npairs; pair += totw) {
        const int t0 = 2 * pair, t1 = 2 * pair + 1;

        encode_tile(st0H, st0L, row, half, t0 * 16 + row, x, v, table);
        encode_tile(st1H, st1L, row, half, t1 * 16 + row, x, v, table);
        __syncwarp();

        // ---------------- A1 fragments ----------------
        uint32_t a1h[2][3][4], a1l[2][3][4];
        #pragma unroll
        for (int k = 0; k < 3; k++) {
            ldsm4(a1h[0][k], uSt0H + aofs + 32 * k);
            ldsm4(a1l[0][k], uSt0L + aofs + 32 * k);
            ldsm4(a1h[1][k], uSt1H + aofs + 32 * k);
            ldsm4(a1l[1][k], uSt1L + aofs + 32 * k);
        }

        // ---------------- L1 ----------------
        uint32_t a2h[2][4][4], a2l[2][4][4];
        #pragma unroll
        for (int m = 0; m < 4; m++) {
            float c[2][2][4];   // [u][tile]
            #pragma unroll
            for (int u = 0; u < 2; u++) {
                const uint32_t jb = (2 * m + u) * (8 * 112);
                float *c0 = c[u][0], *c1 = c[u][1];
                #pragma unroll
                for (int q = 0; q < 4; q++) { c0[q] = 0.0f; c1[q] = 0.0f; }
                pass2d(c0, c1, a1h[0], a1l[0], a1h[1], a1l[1], 0, uW1h + jb, uW1l + jb);
                pass1d(c0, c1, a1h[0][2], a1l[0][2], a1h[1][2], a1l[1][2],
                       uW1hb + jb, uW1lb + jb);
            }
            #pragma unroll
            for (int tt = 0; tt < 2; tt++) {
                a2h[tt][m][0] = bf2r(c[0][tt][0], c[0][tt][1], a2l[tt][m][0]);
                a2h[tt][m][1] = bf2r(c[0][tt][2], c[0][tt][3], a2l[tt][m][1]);
                a2h[tt][m][2] = bf2r(c[1][tt][0], c[1][tt][1], a2l[tt][m][2]);
                a2h[tt][m][3] = bf2r(c[1][tt][2], c[1][tt][3], a2l[tt][m][3]);
            }
        }

        // ---------------- L2 ----------------
        uint32_t a3h[2][5][4], a3l[2][5][4];
        #pragma unroll
        for (int m = 0; m < 4; m++) {
            float c[2][2][4];
            #pragma unroll
            for (int u = 0; u < 2; u++) {
                const int j = 2 * m + u;
                const uint32_t jb = j * (8 * 144);
                float *c0 = c[u][0], *c1 = c[u][1];
                const float2 bb = *(const float2*)(sB2 + 8 * j + t2);
                c0[0] = bb.x; c0[1] = bb.y; c0[2] = bb.x; c0[3] = bb.y;
                c1[0] = bb.x; c1[1] = bb.y; c1[2] = bb.x; c1[3] = bb.y;
                pass2d(c0, c1, a2h[0], a2l[0], a2h[1], a2l[1], 0, uW2h + jb, uW2l + jb);
                pass2d(c0, c1, a2h[0], a2l[0], a2h[1], a2l[1], 2,
                       uW2h + jb + 64, uW2l + jb + 64);
            }
            #pragma unroll
            for (int tt = 0; tt < 2; tt++) {
                a3h[tt][m][0] = bf2r(c[0][tt][0], c[0][tt][1], a3l[tt][m][0]);
                a3h[tt][m][1] = bf2r(c[0][tt][2], c[0][tt][3], a3l[tt][m][1]);
                a3h[tt][m][2] = bf2r(c[1][tt][0], c[1][tt][1], a3l[tt][m][2]);
                a3h[tt][m][3] = bf2r(c[1][tt][2], c[1][tt][3], a3l[tt][m][3]);
            }
        }
        {   // sigma n-tile
            float c0[4], c1[4];
            const float2 bb = *(const float2*)(sB2 + 64 + t2);
            c0[0] = bb.x; c0[1] = bb.y; c0[2] = bb.x; c0[3] = bb.y;
            c1[0] = bb.x; c1[1] = bb.y; c1[2] = bb.x; c1[3] = bb.y;
            const uint32_t jb = 8 * (8 * 144);
            pass2d(c0, c1, a2h[0], a2l[0], a2h[1], a2l[1], 0, uW2h + jb, uW2l + jb);
            pass2d(c0, c1, a2h[0], a2l[0], a2h[1], a2l[1], 2, uW2h + jb + 64, uW2l + jb + 64);
            if ((lane & 3) == 0) {
                out[t0 * 16 + g]     = __expf(c0[0]);
                out[t0 * 16 + g + 8] = __expf(c0[2]);
                out[t1 * 16 + g]     = __expf(c1[0]);
                out[t1 * 16 + g + 8] = __expf(c1[2]);
            }
        }
        // SH fragments
        ldsm4(a3h[0][4], uSt0H + aofs + 96);
        ldsm4(a3l[0][4], uSt0L + aofs + 96);
        ldsm4(a3h[1][4], uSt1H + aofs + 96);
        ldsm4(a3l[1][4], uSt1L + aofs + 96);

        // ---------------- L3 ----------------
        uint32_t a4h[2][4][4], a4l[2][4][4];
        #pragma unroll
        for (int m = 0; m < 4; m++) {
            float c[2][2][4];
            #pragma unroll
            for (int u = 0; u < 2; u++) {
                const uint32_t jb = (2 * m + u) * (8 * 176);
                float *c0 = c[u][0], *c1 = c[u][1];
                #pragma unroll
                for (int q = 0; q < 4; q++) { c0[q] = 0.0f; c1[q] = 0.0f; }
                pass2d(c0, c1, a3h[0], a3l[0], a3h[1], a3l[1], 0, uW3h + jb, uW3l + jb);
                pass2d(c0, c1, a3h[0], a3l[0], a3h[1], a3l[1], 2,
                       uW3h + jb + 64, uW3l + jb + 64);
                pass1d(c0, c1, a3h[0][4], a3l[0][4], a3h[1][4], a3l[1][4],
                       uW3hb + jb, uW3lb + jb);
            }
            #pragma unroll
            for (int tt = 0; tt < 2; tt++) {
                a4h[tt][m][0] = bf2r(c[0][tt][0], c[0][tt][1], a4l[tt][m][0]);
                a4h[tt][m][1] = bf2r(c[0][tt][2], c[0][tt][3], a4l[tt][m][1]);
                a4h[tt][m][2] = bf2r(c[1][tt][0], c[1][tt][1], a4l[tt][m][2]);
                a4h[tt][m][3] = bf2r(c[1][tt][2], c[1][tt][3], a4l[tt][m][3]);
            }
        }

        // ---------------- L4 + rgb ----------------
        {
            float c0[4], c1[4];
            const float2 bb = *(const float2*)(sB4 + t2);
            c0[0] = bb.x; c0[1] = bb.y; c0[2] = bb.x; c0[3] = bb.y;
            c1[0] = bb.x; c1[1] = bb.y; c1[2] = bb.x; c1[3] = bb.y;
            pass2d(c0, c1, a4h[0], a4l[0], a4h[1], a4l[1], 0, uW4h, uW4l);
            pass2d(c0, c1, a4h[0], a4l[0], a4h[1], a4l[1], 2, uW4h + 64, uW4l + 64);
            const int p0 = t0 * 16 + g, p1 = t1 * 16 + g;
            if ((lane & 3) == 0) {
                out[n + 3 * p0 + 0]       = sigmoidf_(c0[0]);
                out[n + 3 * p0 + 1]       = sigmoidf_(c0[1]);
                out[n + 3 * (p0 + 8) + 0] = sigmoidf_(c0[2]);
                out[n + 3 * (p0 + 8) + 1] = sigmoidf_(c0[3]);
                out[n + 3 * p1 + 0]       = sigmoidf_(c1[0]);
                out[n + 3 * p1 + 1]       = sigmoidf_(c1[1]);
                out[n + 3 * (p1 + 8) + 0] = sigmoidf_(c1[2]);
                out[n + 3 * (p1 + 8) + 1] = sigmoidf_(c1[3]);
            } else if ((lane & 3) == 1) {
                out[n + 3 * p0 + 2]       = sigmoidf_(c0[0]);
                out[n + 3 * (p0 + 8) + 2] = sigmoidf_(c0[2]);
                out[n + 3 * p1 + 2]       = sigmoidf_(c1[0]);
                out[n + 3 * (p1 + 8) + 2] = sigmoidf_(c1[2]);
            }
        }
        __syncwarp();
    }
}

extern "C" void kernel_launch(void* const* d_in, const int* in_sizes, int n_in,
                              void* d_out, int out_size)
{
    const float* x     = (const float*)d_in[0];
    const float* v     = (const float*)d_in[1];
    const float* table = (const float*)d_in[3];
    const float* dw1   = (const float*)d_in[4];
    const float* db1   = (const float*)d_in[5];
    const float* dw2   = (const float*)d_in[6];
    const float* db2   = (const float*)d_in[7];
    const float* rw1   = (const float*)d_in[8];
    const float* rb1   = (const float*)d_in[9];
    const float* rw2   = (const float*)d_in[10];
    const float* rb2   = (const float*)d_in[11];
    float* out = (float*)d_out;

    const int n = in_sizes[0] / 3;

    cudaFuncSetAttribute(nerf_mma3, cudaFuncAttributeMaxDynamicSharedMemorySize, SMEM_DYN);

    prep_weights<<<1, 256>>>(dw1, db1, dw2, db2, rw1, rb1, rw2, rb2);
    nerf_mma3<<<148, 256, SMEM_DYN>>>(x, v, table, out, n);
}

// round 7
// speedup vs baseline: 1.1667x; 1.1667x over previous
#include <cuda_runtime.h>
#include <cuda_bf16.h>
#include <cstdint>

// ============================================================================
// GridNeRF forward: register-chained mma.sync.m16n8k16 (bf16 hi/lo => ~fp32).
// Per warp-tile: 16 points. (R5 structure + paired STS + hoisted constants.)
//   L1: A1[16,48] @ W1t -> 8 n8 (bias folded at col 27 == 1)
//   L2: H1[16,64] @ W2t -> 9 n8 (cols0..63 feat perm, col64 sigma)
//   L3: A3[16,80] @ W3t -> 8 n8 (A3 = feat ++ SH ++ 1 ++ 0, bias row73)
//   L4: H3[16,64] @ W4t -> 1 n8 (cols0..2 -> sigmoid rgb)
// 3 MMA passes per k-tile: Ah*Bh + Al*Bh + Ah*Bl.
// ============================================================================

constexpr int TSZ = 1 << 19;

constexpr int sW1 = 56, sW2 = 72, sW3 = 88, sW4 = 72;   // elem strides [N][K]
constexpr int oW1h = 0;
constexpr int oW1l = oW1h + 64 * sW1;
constexpr int oW2h = oW1l + 64 * sW1;
constexpr int oW2l = oW2h + 72 * sW2;
constexpr int oW3h = oW2l + 72 * sW2;
constexpr int oW3l = oW3h + 64 * sW3;
constexpr int oW4h = oW3l + 64 * sW3;
constexpr int oW4l = oW4h + 8 * sW4;
constexpr int W_ELEMS = oW4l + 8 * sW4;

__device__ __align__(16) __nv_bfloat16 g_w[W_ELEMS];
__device__ __align__(16) float g_b2[72];
__device__ __align__(16) float g_b4[8];

constexpr int oSB2B = 59904;
constexpr int oSB4B = 60192;
constexpr int oSTB  = 60224;              // per-warp staging: hi 2304 + lo 2304
constexpr int SMEM_DYN = oSTB + 8 * 4608; // 97088

// ---------------- PTX helpers ----------------
__device__ __forceinline__ uint32_t smem_u32(const void* p) {
    uint32_t a;
    asm("{ .reg .u64 t; cvta.to.shared.u64 t, %1; cvt.u32.u64 %0, t; }"
        : "=r"(a) : "l"(p));
    return a;
}
__device__ __forceinline__ void ldsm4(uint32_t* r, uint32_t addr) {
    asm volatile("ldmatrix.sync.aligned.m8n8.x4.shared.b16 {%0,%1,%2,%3}, [%4];"
        : "=r"(r[0]), "=r"(r[1]), "=r"(r[2]), "=r"(r[3]) : "r"(addr));
}
__device__ __forceinline__ void ldsm2(uint32_t& r0, uint32_t& r1, uint32_t addr) {
    asm volatile("ldmatrix.sync.aligned.m8n8.x2.shared.b16 {%0,%1}, [%2];"
        : "=r"(r0), "=r"(r1) : "r"(addr));
}
#define MMA4(c, a, b0_, b1_) \
    asm volatile("mma.sync.aligned.m16n8k16.row.col.f32.bf16.bf16.f32 " \
        "{%0,%1,%2,%3},{%4,%5,%6,%7},{%8,%9},{%0,%1,%2,%3};" \
        : "+f"((c)[0]), "+f"((c)[1]), "+f"((c)[2]), "+f"((c)[3]) \
        : "r"((a)[0]), "r"((a)[1]), "r"((a)[2]), "r"((a)[3]), "r"(b0_), "r"(b1_))

__device__ __forceinline__ void pass2(float* c, const uint32_t (*ah)[4],
                                      const uint32_t (*al)[4], int kt0,
                                      uint32_t bh_addr, uint32_t bl_addr) {
    uint32_t bb[4];
    ldsm4(bb, bh_addr);
    MMA4(c, ah[kt0], bb[0], bb[1]);
    MMA4(c, ah[kt0 + 1], bb[2], bb[3]);
    MMA4(c, al[kt0], bb[0], bb[1]);
    MMA4(c, al[kt0 + 1], bb[2], bb[3]);
    ldsm4(bb, bl_addr);
    MMA4(c, ah[kt0], bb[0], bb[1]);
    MMA4(c, ah[kt0 + 1], bb[2], bb[3]);
}
__device__ __forceinline__ void pass1(float* c, const uint32_t* ah, const uint32_t* al,
                                      uint32_t bh_addr, uint32_t bl_addr) {
    uint32_t r0, r1;
    ldsm2(r0, r1, bh_addr);
    MMA4(c, ah, r0, r1);
    MMA4(c, al, r0, r1);
    ldsm2(r0, r1, bl_addr);
    MMA4(c, ah, r0, r1);
}

__device__ __forceinline__ uint32_t bf2r(float a, float b, uint32_t& lo) {
    a = fmaxf(a, 0.0f); b = fmaxf(b, 0.0f);
    __nv_bfloat162 h = __floats2bfloat162_rn(a, b);
    __nv_bfloat162 l = __floats2bfloat162_rn(a - __bfloat162float(h.x),
                                             b - __bfloat162float(h.y));
    lo = *reinterpret_cast<uint32_t*>(&l);
    return *reinterpret_cast<uint32_t*>(&h);
}

// ---------------- weight prep ----------------
__device__ __forceinline__ void put_w(int hi, int lo, float w) {
    __nv_bfloat16 h = __float2bfloat16(w);
    g_w[hi] = h;
    g_w[lo] = __float2bfloat16(w - __bfloat162float(h));
}

__global__ void prep_weights(const float* __restrict__ dw1, const float* __restrict__ db1,
                             const float* __restrict__ dw2, const float* __restrict__ db2,
                             const float* __restrict__ rw1, const float* __restrict__ rb1,
                             const float* __restrict__ rw2, const float* __restrict__ rb2)
{
    const int tid = threadIdx.x;
    for (int i = tid; i < W_ELEMS; i += 256) g_w[i] = __float2bfloat16(0.0f);
    __syncthreads();
    // W1t[n][k], k-mapping: 0..26 = dw1 rows 0..26; 27 = db1 (bias col);
    //                       28..47 = dw1 rows 27..46
    for (int i = tid; i < 64 * 48; i += 256) {
        int nn = i / 48, k = i % 48;
        float w;
        if (k < 27)       w = dw1[k * 64 + nn];
        else if (k == 27) w = db1[nn];
        else              w = dw1[(k - 1) * 64 + nn];
        put_w(oW1h + nn * sW1 + k, oW1l + nn * sW1 + k, w);
    }
    for (int i = tid; i < 65 * 64; i += 256) {
        int nn = i / 64, k = i % 64;
        float w = (nn < 64) ? dw2[k * 65 + nn + 1] : dw2[k * 65];
        put_w(oW2h + nn * sW2 + k, oW2l + nn * sW2 + k, w);
    }
    for (int i = tid; i < 64 * 74; i += 256) {
        int nn = i / 74, k = i % 74;
        float w = (k < 73) ? rw1[k * 64 + nn] : rb1[nn];
        put_w(oW3h + nn * sW3 + k, oW3l + nn * sW3 + k, w);
    }
    for (int i = tid; i < 3 * 64; i += 256) {
        int nn = i / 64, k = i % 64;
        put_w(oW4h + nn * sW4 + k, oW4l + nn * sW4 + k, rw2[k * 3 + nn]);
    }
    if (tid < 72) g_b2[tid] = (tid < 64) ? db2[tid + 1] : ((tid == 64) ? db2[0] : 0.0f);
    if (tid < 8)  g_b4[tid] = (tid < 3) ? rb2[tid] : 0.0f;
}

// paired staging store: cols (c, c+1), c even; hi and lo buffers
__device__ __forceinline__ void put_st2(char* H, char* L, uint32_t rbase,
                                        int c, float a, float b) {
    __nv_bfloat162 h = __floats2bfloat162_rn(a, b);
    __nv_bfloat162 l = __floats2bfloat162_rn(a - __bfloat162float(h.x),
                                             b - __bfloat162float(h.y));
    *(uint32_t*)(H + rbase + c * 2) = *reinterpret_cast<uint32_t*>(&h);
    *(uint32_t*)(L + rbase + c * 2) = *reinterpret_cast<uint32_t*>(&l);
}

__device__ __forceinline__ float sigmoidf_(float z) {
    return 1.0f / (1.0f + __expf(-z));
}

// ---------------- main kernel ----------------
__global__ void __launch_bounds__(256, 2) nerf_mma2(
    const float* __restrict__ x, const float* __restrict__ v,
    const float* __restrict__ table, float* __restrict__ out, int n)
{
    extern __shared__ __align__(16) unsigned char S[];
    const int tid = threadIdx.x, wid = tid >> 5, lane = tid & 31;

    for (int i = tid; i < 59904 / 16; i += 256)
        ((uint4*)S)[i] = ((const uint4*)g_w)[i];
    float* sB2 = (float*)(S + oSB2B);
    float* sB4 = (float*)(S + oSB4B);
    if (tid < 72) sB2[tid] = g_b2[tid];
    if (tid < 8)  sB4[tid] = g_b4[tid];
    __syncthreads();

    const uint32_t uS = smem_u32(S);
    const int g = lane >> 2, t2 = (lane & 3) * 2;
    const int row = lane >> 1, half = lane & 1;

    char* stH = (char*)(S + oSTB + wid * 4608);
    char* stL = stH + 2304;
    const uint32_t uStH = uS + oSTB + wid * 4608;
    const uint32_t uStL = uStH + 2304;
    const uint32_t rbase = (uint32_t)row * 144;

    const uint32_t aofs   = (lane & 15) * 144 + (lane >> 4) * 16;
    const uint32_t bo112  = (lane & 7) * 112 + (lane >> 3) * 16;
    const uint32_t bo112b = (lane & 7) * 112 + ((lane >> 3) & 1) * 16;
    const uint32_t bo144  = (lane & 7) * 144 + (lane >> 3) * 16;
    const uint32_t bo176  = (lane & 7) * 176 + (lane >> 3) * 16;
    const uint32_t bo176b = (lane & 7) * 176 + ((lane >> 3) & 1) * 16;

    const uint32_t uW1h  = uS + oW1h * 2 + bo112,        uW1l  = uS + oW1l * 2 + bo112;
    const uint32_t uW1hb = uS + oW1h * 2 + 64 + bo112b,  uW1lb = uS + oW1l * 2 + 64 + bo112b;
    const uint32_t uW2h  = uS + oW2h * 2 + bo144,        uW2l  = uS + oW2l * 2 + bo144;
    const uint32_t uW3h  = uS + oW3h * 2 + bo176,        uW3l  = uS + oW3l * 2 + bo176;
    const uint32_t uW3hb = uS + oW3h * 2 + 128 + bo176b, uW3lb = uS + oW3l * 2 + 128 + bo176b;
    const uint32_t uW4h  = uS + oW4h * 2 + bo144,        uW4l  = uS + oW4l * 2 + bo144;

    // one-time: zero staging cols 58..63 (never rewritten)
    if (half == 0) {
        put_st2(stH, stL, rbase, 58, 0.0f, 0.0f);
        put_st2(stH, stL, rbase, 60, 0.0f, 0.0f);
        put_st2(stH, stL, rbase, 62, 0.0f, 0.0f);
    }

    const int ntiles = n >> 4;
    const int totw = gridDim.x * 8;

    for (int tile = blockIdx.x * 8 + wid; tile < ntiles; tile += totw) {
        const int p = tile * 16 + row;
        const float px0 = x[3 * p], px1 = x[3 * p + 1], px2 = x[3 * p + 2];

        // ---------------- encoding -> staging (paired stores) ----------------
        if (half == 0) {
            float e[28];
            e[0] = px0; e[1] = px1; e[2] = px2;
            const float pv[2] = {px0, px1};
            #pragma unroll
            for (int d = 0; d < 2; d++) {
                float fm = 1.0f;
                #pragma unroll
                for (int fr = 0; fr < 6; fr++) {
                    __sincosf(pv[d] * fm, &e[3 + d * 12 + fr], &e[9 + d * 12 + fr]);
                    fm *= 2.0f;
                }
            }
            e[27] = 1.0f;  // L1 bias column
            #pragma unroll
            for (int q = 0; q < 14; q++)
                put_st2(stH, stL, rbase, 2 * q, e[2 * q], e[2 * q + 1]);

            // SH -> cols 48..56; 1.0 (L3 bias) at 57
            const float vx = v[3 * p], vy = v[3 * p + 1], vz = v[3 * p + 2];
            put_st2(stH, stL, rbase, 48, 0.28209479177387814f, -0.4886025119029199f * vy);
            put_st2(stH, stL, rbase, 50,  0.4886025119029199f * vz, -0.4886025119029199f * vx);
            put_st2(stH, stL, rbase, 52,  1.0925484305920792f * vx * vy,
                                         -1.0925484305920792f * vy * vz);
            put_st2(stH, stL, rbase, 54,  0.9461746957575601f * vz * vz - 0.31539156525252005f,
                                         -1.0925484305920792f * vx * vz);
            put_st2(stH, stL, rbase, 56,  0.5462742152960396f * (vx * vx - vy * vy), 1.0f);
        } else {
            float e[20];   // cols 28..47
            float fm = 1.0f;
            #pragma unroll
            for (int fr = 0; fr < 6; fr++) {
                __sincosf(px2 * fm, &e[fr], &e[6 + fr]);
                fm *= 2.0f;
            }
            const float x01x = (px0 + 1.0f) * 0.5f;
            const float x01y = (px1 + 1.0f) * 0.5f;
            const float x01z = (px2 + 1.0f) * 0.5f;
            const float resf[4] = {33.0f, 43.0f, 56.0f, 74.0f};
            #pragma unroll
            for (int lv = 0; lv < 4; lv++) {
                const float pxx = x01x * resf[lv], pyy = x01y * resf[lv], pzz = x01z * resf[lv];
                const float fx = floorf(pxx), fy = floorf(pyy), fz = floorf(pzz);
                const float tx = pxx - fx, ty = pyy - fy, tz = pzz - fz;
                const float wx = tx * tx * (3.0f - 2.0f * tx);
                const float wy = ty * ty * (3.0f - 2.0f * ty);
                const float wz = tz * tz * (3.0f - 2.0f * tz);
                const unsigned cx = (unsigned)fx, cy = (unsigned)fy, cz = (unsigned)fz;
                const float* tb = table + (size_t)lv * (TSZ * 2);
                float f0 = 0.0f, f1 = 0.0f;
                #pragma unroll
                for (int c = 0; c < 8; c++) {
                    const unsigned hx = cx + (c & 1);
                    const unsigned hy = cy + ((c >> 1) & 1);
                    const unsigned hz = cz + ((c >> 2) & 1);
                    const unsigned hsh = (hx ^ (hy * 2654435761u) ^ (hz * 805459861u)) & (unsigned)(TSZ - 1);
                    const float cw = ((c & 1) ? wx : 1.0f - wx)
                                   * (((c >> 1) & 1) ? wy : 1.0f - wy)
                                   * (((c >> 2) & 1) ? wz : 1.0f - wz);
                    const float2 tv = __ldg(reinterpret_cast<const float2*>(tb + 2u * hsh));
                    f0 = fmaf(tv.x, cw, f0);
                    f1 = fmaf(tv.y, cw, f1);
                }
                e[12 + 2 * lv] = f0;
                e[13 + 2 * lv] = f1;
            }
            #pragma unroll
            for (int q = 0; q < 10; q++)
                put_st2(stH, stL, rbase, 28 + 2 * q, e[2 * q], e[2 * q + 1]);
        }
        __syncwarp();

        // ---------------- A1 fragments ----------------
        uint32_t a1h[3][4], a1l[3][4];
        ldsm4(a1h[0], uStH + aofs);      ldsm4(a1h[1], uStH + aofs + 32);
        ldsm4(a1h[2], uStH + aofs + 64);
        ldsm4(a1l[0], uStL + aofs);      ldsm4(a1l[1], uStL + aofs + 32);
        ldsm4(a1l[2], uStL + aofs + 64);

        // ---------------- L1 ----------------
        uint32_t a2h[4][4], a2l[4][4];
        #pragma unroll
        for (int m = 0; m < 4; m++) {
            float c[2][4];
            #pragma unroll
            for (int u = 0; u < 2; u++) {
                const uint32_t jb = (2 * m + u) * (8 * 112);
                float* cc = c[u];
                cc[0] = cc[1] = cc[2] = cc[3] = 0.0f;
                pass2(cc, a1h, a1l, 0, uW1h + jb, uW1l + jb);
                pass1(cc, a1h[2], a1l[2], uW1hb + jb, uW1lb + jb);
            }
            a2h[m][0] = bf2r(c[0][0], c[0][1], a2l[m][0]);
            a2h[m][1] = bf2r(c[0][2], c[0][3], a2l[m][1]);
            a2h[m][2] = bf2r(c[1][0], c[1][1], a2l[m][2]);
            a2h[m][3] = bf2r(c[1][2], c[1][3], a2l[m][3]);
        }

        // ---------------- L2 ----------------
        uint32_t a3h[5][4], a3l[5][4];
        #pragma unroll
        for (int m = 0; m < 4; m++) {
            float c[2][4];
            #pragma unroll
            for (int u = 0; u < 2; u++) {
                const int j = 2 * m + u;
                const uint32_t jb = j * (8 * 144);
                float* cc = c[u];
                const float2 bb = *(const float2*)(sB2 + 8 * j + t2);
                cc[0] = bb.x; cc[1] = bb.y; cc[2] = bb.x; cc[3] = bb.y;
                pass2(cc, a2h, a2l, 0, uW2h + jb, uW2l + jb);
                pass2(cc, a2h, a2l, 2, uW2h + jb + 64, uW2l + jb + 64);
            }
            a3h[m][0] = bf2r(c[0][0], c[0][1], a3l[m][0]);
            a3h[m][1] = bf2r(c[0][2], c[0][3], a3l[m][1]);
            a3h[m][2] = bf2r(c[1][0], c[1][1], a3l[m][2]);
            a3h[m][3] = bf2r(c[1][2], c[1][3], a3l[m][3]);
        }
        {   // sigma n-tile
            float cc[4];
            const float2 bb = *(const float2*)(sB2 + 64 + t2);
            cc[0] = bb.x; cc[1] = bb.y; cc[2] = bb.x; cc[3] = bb.y;
            const uint32_t jb = 8 * (8 * 144);
            pass2(cc, a2h, a2l, 0, uW2h + jb, uW2l + jb);
            pass2(cc, a2h, a2l, 2, uW2h + jb + 64, uW2l + jb + 64);
            if ((lane & 3) == 0) {
                out[tile * 16 + g]     = __expf(cc[0]);
                out[tile * 16 + g + 8] = __expf(cc[2]);
            }
        }
        ldsm4(a3h[4], uStH + aofs + 96);
        ldsm4(a3l[4], uStL + aofs + 96);

        // ---------------- L3 ----------------
        uint32_t a4h[4][4], a4l[4][4];
        #pragma unroll
        for (int m = 0; m < 4; m++) {
            float c[2][4];
            #pragma unroll
            for (int u = 0; u < 2; u++) {
                const uint32_t jb = (2 * m + u) * (8 * 176);
                float* cc = c[u];
                cc[0] = cc[1] = cc[2] = cc[3] = 0.0f;
                pass2(cc, a3h, a3l, 0, uW3h + jb, uW3l + jb);
                pass2(cc, a3h, a3l, 2, uW3h + jb + 64, uW3l + jb + 64);
                pass1(cc, a3h[4], a3l[4], uW3hb + jb, uW3lb + jb);
            }
            a4h[m][0] = bf2r(c[0][0], c[0][1], a4l[m][0]);
            a4h[m][1] = bf2r(c[0][2], c[0][3], a4l[m][1]);
            a4h[m][2] = bf2r(c[1][0], c[1][1], a4l[m][2]);
            a4h[m][3] = bf2r(c[1][2], c[1][3], a4l[m][3]);
        }

        // ---------------- L4 + rgb ----------------
        {
            float cc[4];
            const float2 bb = *(const float2*)(sB4 + t2);
            cc[0] = bb.x; cc[1] = bb.y; cc[2] = bb.x; cc[3] = bb.y;
            pass2(cc, a4h, a4l, 0, uW4h, uW4l);
            pass2(cc, a4h, a4l, 2, uW4h + 64, uW4l + 64);
            const int pg = tile * 16 + g;
            if ((lane & 3) == 0) {
                out[n + 3 * pg + 0]       = sigmoidf_(cc[0]);
                out[n + 3 * pg + 1]       = sigmoidf_(cc[1]);
                out[n + 3 * (pg + 8) + 0] = sigmoidf_(cc[2]);
                out[n + 3 * (pg + 8) + 1] = sigmoidf_(cc[3]);
            } else if ((lane & 3) == 1) {
                out[n + 3 * pg + 2]       = sigmoidf_(cc[0]);
                out[n + 3 * (pg + 8) + 2] = sigmoidf_(cc[2]);
            }
        }
        __syncwarp();
    }
}

extern "C" void kernel_launch(void* const* d_in, const int* in_sizes, int n_in,
                              void* d_out, int out_size)
{
    const float* x     = (const float*)d_in[0];
    const float* v     = (const float*)d_in[1];
    const float* table = (const float*)d_in[3];
    const float* dw1   = (const float*)d_in[4];
    const float* db1   = (const float*)d_in[5];
    const float* dw2   = (const float*)d_in[6];
    const float* db2   = (const float*)d_in[7];
    const float* rw1   = (const float*)d_in[8];
    const float* rb1   = (const float*)d_in[9];
    const float* rw2   = (const float*)d_in[10];
    const float* rb2   = (const float*)d_in[11];
    float* out = (float*)d_out;

    const int n = in_sizes[0] / 3;

    cudaFuncSetAttribute(nerf_mma2, cudaFuncAttributeMaxDynamicSharedMemorySize, SMEM_DYN);

    prep_weights<<<1, 256>>>(dw1, db1, dw2, db2, rw1, rb1, rw2, rb2);
    nerf_mma2<<<296, 256, SMEM_DYN>>>(x, v, table, out, n);
}

// round 8
// speedup vs baseline: 1.5533x; 1.3314x over previous
#include <cuda_runtime.h>
#include <cuda_fp16.h>
#include <cstdint>

// ============================================================================
// GridNeRF forward: register-chained mma.sync.m16n8k16 fp16.
// Activations split hi/lo fp16 (exact); weights single fp16 (err ~2^-12/layer).
// 2 MMA passes per k-tile: Ah*W + Al*W.
//   L1: A1[16,48] @ W1t -> 8 n8 (bias folded at col 27 == 1)
//   L2: H1[16,64] @ W2t -> 9 n8 (cols0..63 feat perm, col64 sigma)
//   L3: A3[16,80] @ W3t -> 8 n8 (A3 = feat ++ SH ++ 1 ++ 0, bias row73)
//   L4: H3[16,64] @ W4t -> 1 n8 (cols0..2 -> sigmoid rgb)
// ============================================================================

constexpr int TSZ = 1 << 19;

constexpr int sW1 = 56, sW2 = 72, sW3 = 88, sW4 = 72;   // elem strides [N][K]
constexpr int oW1 = 0;
constexpr int oW2 = oW1 + 64 * sW1;     // 3584
constexpr int oW3 = oW2 + 72 * sW2;     // 8768
constexpr int oW4 = oW3 + 64 * sW3;     // 14400
constexpr int W_ELEMS = oW4 + 8 * sW4;  // 14976 elems = 29952 B

__device__ __align__(16) __half g_w[W_ELEMS];
__device__ __align__(16) float g_b2[72];
__device__ __align__(16) float g_b4[8];

constexpr int oSB2B = 29952;
constexpr int oSB4B = 30240;
constexpr int oSTB  = 30272;              // per-warp staging: hi 2304 + lo 2304
constexpr int SMEM_DYN = oSTB + 8 * 4608; // 67136

// ---------------- PTX helpers ----------------
__device__ __forceinline__ uint32_t smem_u32(const void* p) {
    uint32_t a;
    asm("{ .reg .u64 t; cvta.to.shared.u64 t, %1; cvt.u32.u64 %0, t; }"
        : "=r"(a) : "l"(p));
    return a;
}
__device__ __forceinline__ void ldsm4(uint32_t* r, uint32_t addr) {
    asm volatile("ldmatrix.sync.aligned.m8n8.x4.shared.b16 {%0,%1,%2,%3}, [%4];"
        : "=r"(r[0]), "=r"(r[1]), "=r"(r[2]), "=r"(r[3]) : "r"(addr));
}
__device__ __forceinline__ void ldsm2(uint32_t& r0, uint32_t& r1, uint32_t addr) {
    asm volatile("ldmatrix.sync.aligned.m8n8.x2.shared.b16 {%0,%1}, [%2];"
        : "=r"(r0), "=r"(r1) : "r"(addr));
}
#define MMA4(c, a, b0_, b1_) \
    asm volatile("mma.sync.aligned.m16n8k16.row.col.f32.f16.f16.f32 " \
        "{%0,%1,%2,%3},{%4,%5,%6,%7},{%8,%9},{%0,%1,%2,%3};" \
        : "+f"((c)[0]), "+f"((c)[1]), "+f"((c)[2]), "+f"((c)[3]) \
        : "r"((a)[0]), "r"((a)[1]), "r"((a)[2]), "r"((a)[3]), "r"(b0_), "r"(b1_))

// 2 k-tiles: one ldsm4 feeds 4 MMAs (hi + lo activation passes)
__device__ __forceinline__ void pass2(float* c, const uint32_t (*ah)[4],
                                      const uint32_t (*al)[4], int kt0,
                                      uint32_t b_addr) {
    uint32_t bb[4];
    ldsm4(bb, b_addr);
    MMA4(c, ah[kt0], bb[0], bb[1]);
    MMA4(c, ah[kt0 + 1], bb[2], bb[3]);
    MMA4(c, al[kt0], bb[0], bb[1]);
    MMA4(c, al[kt0 + 1], bb[2], bb[3]);
}
// single k-tile: one ldsm2 feeds 2 MMAs
__device__ __forceinline__ void pass1(float* c, const uint32_t* ah, const uint32_t* al,
                                      uint32_t b_addr) {
    uint32_t r0, r1;
    ldsm2(r0, r1, b_addr);
    MMA4(c, ah, r0, r1);
    MMA4(c, al, r0, r1);
}

// relu + split fp32 pair -> fp16 hi (ret) and lo (out param)
__device__ __forceinline__ uint32_t f16r(float a, float b, uint32_t& lo) {
    a = fmaxf(a, 0.0f); b = fmaxf(b, 0.0f);
    __half2 h = __floats2half2_rn(a, b);
    float2 hf = __half22float2(h);
    __half2 l = __floats2half2_rn(a - hf.x, b - hf.y);
    lo = *reinterpret_cast<uint32_t*>(&l);
    return *reinterpret_cast<uint32_t*>(&h);
}

// ---------------- weight prep ----------------
__global__ void prep_weights(const float* __restrict__ dw1, const float* __restrict__ db1,
                             const float* __restrict__ dw2, const float* __restrict__ db2,
                             const float* __restrict__ rw1, const float* __restrict__ rb1,
                             const float* __restrict__ rw2, const float* __restrict__ rb2)
{
    const int tid = threadIdx.x;
    for (int i = tid; i < W_ELEMS; i += 256) g_w[i] = __float2half_rn(0.0f);
    __syncthreads();
    // W1t[n][k], k-mapping: 0..26 = dw1 rows 0..26; 27 = db1; 28..47 = dw1 rows 27..46
    for (int i = tid; i < 64 * 48; i += 256) {
        int nn = i / 48, k = i % 48;
        float w;
        if (k < 27)       w = dw1[k * 64 + nn];
        else if (k == 27) w = db1[nn];
        else              w = dw1[(k - 1) * 64 + nn];
        g_w[oW1 + nn * sW1 + k] = __float2half_rn(w);
    }
    for (int i = tid; i < 65 * 64; i += 256) {
        int nn = i / 64, k = i % 64;
        float w = (nn < 64) ? dw2[k * 65 + nn + 1] : dw2[k * 65];
        g_w[oW2 + nn * sW2 + k] = __float2half_rn(w);
    }
    for (int i = tid; i < 64 * 74; i += 256) {
        int nn = i / 74, k = i % 74;
        float w = (k < 73) ? rw1[k * 64 + nn] : rb1[nn];
        g_w[oW3 + nn * sW3 + k] = __float2half_rn(w);
    }
    for (int i = tid; i < 3 * 64; i += 256) {
        int nn = i / 64, k = i % 64;
        g_w[oW4 + nn * sW4 + k] = __float2half_rn(rw2[k * 3 + nn]);
    }
    if (tid < 72) g_b2[tid] = (tid < 64) ? db2[tid + 1] : ((tid == 64) ? db2[0] : 0.0f);
    if (tid < 8)  g_b4[tid] = (tid < 3) ? rb2[tid] : 0.0f;
}

// paired staging store: cols (c, c+1), c even; fp16 hi and lo buffers
__device__ __forceinline__ void put_st2(char* H, char* L, uint32_t rbase,
                                        int c, float a, float b) {
    __half2 h = __floats2half2_rn(a, b);
    float2 hf = __half22float2(h);
    __half2 l = __floats2half2_rn(a - hf.x, b - hf.y);
    *(uint32_t*)(H + rbase + c * 2) = *reinterpret_cast<uint32_t*>(&h);
    *(uint32_t*)(L + rbase + c * 2) = *reinterpret_cast<uint32_t*>(&l);
}

__device__ __forceinline__ float sigmoidf_(float z) {
    return 1.0f / (1.0f + __expf(-z));
}

// ---------------- main kernel ----------------
__global__ void __launch_bounds__(256, 2) nerf_mma4(
    const float* __restrict__ x, const float* __restrict__ v,
    const float* __restrict__ table, float* __restrict__ out, int n)
{
    extern __shared__ __align__(16) unsigned char S[];
    const int tid = threadIdx.x, wid = tid >> 5, lane = tid & 31;

    for (int i = tid; i < 29952 / 16; i += 256)
        ((uint4*)S)[i] = ((const uint4*)g_w)[i];
    float* sB2 = (float*)(S + oSB2B);
    float* sB4 = (float*)(S + oSB4B);
    if (tid < 72) sB2[tid] = g_b2[tid];
    if (tid < 8)  sB4[tid] = g_b4[tid];
    __syncthreads();

    const uint32_t uS = smem_u32(S);
    const int g = lane >> 2, t2 = (lane & 3) * 2;
    const int row = lane >> 1, half = lane & 1;

    char* stH = (char*)(S + oSTB + wid * 4608);
    char* stL = stH + 2304;
    const uint32_t uStH = uS + oSTB + wid * 4608;
    const uint32_t uStL = uStH + 2304;
    const uint32_t rbase = (uint32_t)row * 144;

    const uint32_t aofs   = (lane & 15) * 144 + (lane >> 4) * 16;
    const uint32_t bo112  = (lane & 7) * 112 + (lane >> 3) * 16;
    const uint32_t bo112b = (lane & 7) * 112 + ((lane >> 3) & 1) * 16;
    const uint32_t bo144  = (lane & 7) * 144 + (lane >> 3) * 16;
    const uint32_t bo176  = (lane & 7) * 176 + (lane >> 3) * 16;
    const uint32_t bo176b = (lane & 7) * 176 + ((lane >> 3) & 1) * 16;

    const uint32_t uW1  = uS + oW1 * 2 + bo112;
    const uint32_t uW1b = uS + oW1 * 2 + 64 + bo112b;
    const uint32_t uW2  = uS + oW2 * 2 + bo144;
    const uint32_t uW3  = uS + oW3 * 2 + bo176;
    const uint32_t uW3b = uS + oW3 * 2 + 128 + bo176b;
    const uint32_t uW4  = uS + oW4 * 2 + bo144;

    // one-time: zero staging cols 58..63
    if (half == 0) {
        put_st2(stH, stL, rbase, 58, 0.0f, 0.0f);
        put_st2(stH, stL, rbase, 60, 0.0f, 0.0f);
        put_st2(stH, stL, rbase, 62, 0.0f, 0.0f);
    }

    const int ntiles = n >> 4;
    const int totw = gridDim.x * 8;

    for (int tile = blockIdx.x * 8 + wid; tile < ntiles; tile += totw) {
        const int p = tile * 16 + row;
        const float px0 = x[3 * p], px1 = x[3 * p + 1], px2 = x[3 * p + 2];

        // ---------------- encoding -> staging ----------------
        if (half == 0) {
            float e[28];
            e[0] = px0; e[1] = px1; e[2] = px2;
            const float pv[2] = {px0, px1};
            #pragma unroll
            for (int d = 0; d < 2; d++) {
                float fm = 1.0f;
                #pragma unroll
                for (int fr = 0; fr < 6; fr++) {
                    __sincosf(pv[d] * fm, &e[3 + d * 12 + fr], &e[9 + d * 12 + fr]);
                    fm *= 2.0f;
                }
            }
            e[27] = 1.0f;  // L1 bias column
            #pragma unroll
            for (int q = 0; q < 14; q++)
                put_st2(stH, stL, rbase, 2 * q, e[2 * q], e[2 * q + 1]);

            const float vx = v[3 * p], vy = v[3 * p + 1], vz = v[3 * p + 2];
            put_st2(stH, stL, rbase, 48, 0.28209479177387814f, -0.4886025119029199f * vy);
            put_st2(stH, stL, rbase, 50,  0.4886025119029199f * vz, -0.4886025119029199f * vx);
            put_st2(stH, stL, rbase, 52,  1.0925484305920792f * vx * vy,
                                         -1.0925484305920792f * vy * vz);
            put_st2(stH, stL, rbase, 54,  0.9461746957575601f * vz * vz - 0.31539156525252005f,
                                         -1.0925484305920792f * vx * vz);
            put_st2(stH, stL, rbase, 56,  0.5462742152960396f * (vx * vx - vy * vy), 1.0f);
        } else {
            float e[20];   // cols 28..47
            float fm = 1.0f;
            #pragma unroll
            for (int fr = 0; fr < 6; fr++) {
                __sincosf(px2 * fm, &e[fr], &e[6 + fr]);
                fm *= 2.0f;
            }
            const float x01x = (px0 + 1.0f) * 0.5f;
            const float x01y = (px1 + 1.0f) * 0.5f;
            const float x01z = (px2 + 1.0f) * 0.5f;
            const float resf[4] = {33.0f, 43.0f, 56.0f, 74.0f};
            #pragma unroll
            for (int lv = 0; lv < 4; lv++) {
                const float pxx = x01x * resf[lv], pyy = x01y * resf[lv], pzz = x01z * resf[lv];
                const float fx = floorf(pxx), fy = floorf(pyy), fz = floorf(pzz);
                const float tx = pxx - fx, ty = pyy - fy, tz = pzz - fz;
                const float wx = tx * tx * (3.0f - 2.0f * tx);
                const float wy = ty * ty * (3.0f - 2.0f * ty);
                const float wz = tz * tz * (3.0f - 2.0f * tz);
                const unsigned cx = (unsigned)fx, cy = (unsigned)fy, cz = (unsigned)fz;
                const float* tb = table + (size_t)lv * (TSZ * 2);
                float f0 = 0.0f, f1 = 0.0f;
                #pragma unroll
                for (int c = 0; c < 8; c++) {
                    const unsigned hx = cx + (c & 1);
                    const unsigned hy = cy + ((c >> 1) & 1);
                    const unsigned hz = cz + ((c >> 2) & 1);
                    const unsigned hsh = (hx ^ (hy * 2654435761u) ^ (hz * 805459861u)) & (unsigned)(TSZ - 1);
                    const float cw = ((c & 1) ? wx : 1.0f - wx)
                                   * (((c >> 1) & 1) ? wy : 1.0f - wy)
                                   * (((c >> 2) & 1) ? wz : 1.0f - wz);
                    const float2 tv = __ldg(reinterpret_cast<const float2*>(tb + 2u * hsh));
                    f0 = fmaf(tv.x, cw, f0);
                    f1 = fmaf(tv.y, cw, f1);
                }
                e[12 + 2 * lv] = f0;
                e[13 + 2 * lv] = f1;
            }
            #pragma unroll
            for (int q = 0; q < 10; q++)
                put_st2(stH, stL, rbase, 28 + 2 * q, e[2 * q], e[2 * q + 1]);
        }
        __syncwarp();

        // ---------------- A1 fragments ----------------
        uint32_t a1h[3][4], a1l[3][4];
        ldsm4(a1h[0], uStH + aofs);      ldsm4(a1h[1], uStH + aofs + 32);
        ldsm4(a1h[2], uStH + aofs + 64);
        ldsm4(a1l[0], uStL + aofs);      ldsm4(a1l[1], uStL + aofs + 32);
        ldsm4(a1l[2], uStL + aofs + 64);

        // ---------------- L1 ----------------
        uint32_t a2h[4][4], a2l[4][4];
        #pragma unroll
        for (int m = 0; m < 4; m++) {
            float c[2][4];
            #pragma unroll
            for (int u = 0; u < 2; u++) {
                const uint32_t jb = (2 * m + u) * (8 * 112);
                float* cc = c[u];
                cc[0] = cc[1] = cc[2] = cc[3] = 0.0f;
                pass2(cc, a1h, a1l, 0, uW1 + jb);
                pass1(cc, a1h[2], a1l[2], uW1b + jb);
            }
            a2h[m][0] = f16r(c[0][0], c[0][1], a2l[m][0]);
            a2h[m][1] = f16r(c[0][2], c[0][3], a2l[m][1]);
            a2h[m][2] = f16r(c[1][0], c[1][1], a2l[m][2]);
            a2h[m][3] = f16r(c[1][2], c[1][3], a2l[m][3]);
        }

        // ---------------- L2 ----------------
        uint32_t a3h[5][4], a3l[5][4];
        #pragma unroll
        for (int m = 0; m < 4; m++) {
            float c[2][4];
            #pragma unroll
            for (int u = 0; u < 2; u++) {
                const int j = 2 * m + u;
                const uint32_t jb = j * (8 * 144);
                float* cc = c[u];
                const float2 bb = *(const float2*)(sB2 + 8 * j + t2);
                cc[0] = bb.x; cc[1] = bb.y; cc[2] = bb.x; cc[3] = bb.y;
                pass2(cc, a2h, a2l, 0, uW2 + jb);
                pass2(cc, a2h, a2l, 2, uW2 + jb + 64);
            }
            a3h[m][0] = f16r(c[0][0], c[0][1], a3l[m][0]);
            a3h[m][1] = f16r(c[0][2], c[0][3], a3l[m][1]);
            a3h[m][2] = f16r(c[1][0], c[1][1], a3l[m][2]);
            a3h[m][3] = f16r(c[1][2], c[1][3], a3l[m][3]);
        }
        {   // sigma n-tile
            float cc[4];
            const float2 bb = *(const float2*)(sB2 + 64 + t2);
            cc[0] = bb.x; cc[1] = bb.y; cc[2] = bb.x; cc[3] = bb.y;
            const uint32_t jb = 8 * (8 * 144);
            pass2(cc, a2h, a2l, 0, uW2 + jb);
            pass2(cc, a2h, a2l, 2, uW2 + jb + 64);
            if ((lane & 3) == 0) {
                out[tile * 16 + g]     = __expf(cc[0]);
                out[tile * 16 + g + 8] = __expf(cc[2]);
            }
        }
        ldsm4(a3h[4], uStH + aofs + 96);
        ldsm4(a3l[4], uStL + aofs + 96);

        // ---------------- L3 ----------------
        uint32_t a4h[4][4], a4l[4][4];
        #pragma unroll
        for (int m = 0; m < 4; m++) {
            float c[2][4];
            #pragma unroll
            for (int u = 0; u < 2; u++) {
                const uint32_t jb = (2 * m + u) * (8 * 176);
                float* cc = c[u];
                cc[0] = cc[1] = cc[2] = cc[3] = 0.0f;
                pass2(cc, a3h, a3l, 0, uW3 + jb);
                pass2(cc, a3h, a3l, 2, uW3 + jb + 64);
                pass1(cc, a3h[4], a3l[4], uW3b + jb);
            }
            a4h[m][0] = f16r(c[0][0], c[0][1], a4l[m][0]);
            a4h[m][1] = f16r(c[0][2], c[0][3], a4l[m][1]);
            a4h[m][2] = f16r(c[1][0], c[1][1], a4l[m][2]);
            a4h[m][3] = f16r(c[1][2], c[1][3], a4l[m][3]);
        }

        // ---------------- L4 + rgb ----------------
        {
            float cc[4];
            const float2 bb = *(const float2*)(sB4 + t2);
            cc[0] = bb.x; cc[1] = bb.y; cc[2] = bb.x; cc[3] = bb.y;
            pass2(cc, a4h, a4l, 0, uW4);
            pass2(cc, a4h, a4l, 2, uW4 + 64);
            const int pg = tile * 16 + g;
            if ((lane & 3) == 0) {
                out[n + 3 * pg + 0]       = sigmoidf_(cc[0]);
                out[n + 3 * pg + 1]       = sigmoidf_(cc[1]);
                out[n + 3 * (pg + 8) + 0] = sigmoidf_(cc[2]);
                out[n + 3 * (pg + 8) + 1] = sigmoidf_(cc[3]);
            } else if ((lane & 3) == 1) {
                out[n + 3 * pg + 2]       = sigmoidf_(cc[0]);
                out[n + 3 * (pg + 8) + 2] = sigmoidf_(cc[2]);
            }
        }
        __syncwarp();
    }
}

extern "C" void kernel_launch(void* const* d_in, const int* in_sizes, int n_in,
                              void* d_out, int out_size)
{
    const float* x     = (const float*)d_in[0];
    const float* v     = (const float*)d_in[1];
    const float* table = (const float*)d_in[3];
    const float* dw1   = (const float*)d_in[4];
    const float* db1   = (const float*)d_in[5];
    const float* dw2   = (const float*)d_in[6];
    const float* db2   = (const float*)d_in[7];
    const float* rw1   = (const float*)d_in[8];
    const float* rb1   = (const float*)d_in[9];
    const float* rw2   = (const float*)d_in[10];
    const float* rb2   = (const float*)d_in[11];
    float* out = (float*)d_out;

    const int n = in_sizes[0] / 3;

    cudaFuncSetAttribute(nerf_mma4, cudaFuncAttributeMaxDynamicSharedMemorySize, SMEM_DYN);

    prep_weights<<<1, 256>>>(dw1, db1, dw2, db2, rw1, rb1, rw2, rb2);
    nerf_mma4<<<296, 256, SMEM_DYN>>>(x, v, table, out, n);
}

// round 9
// speedup vs baseline: 1.9670x; 1.2663x over previous
#include <cuda_runtime.h>
#include <cuda_fp16.h>
#include <cstdint>

// ============================================================================
// GridNeRF forward: register-chained mma.sync.m16n8k16, single fp16 operands.
// (Weights fp16 ~2e-4 rel err + activations fp16 ~2e-4 rel err; tol 1e-3.)
//   L1: A1[16,48] @ W1t -> 8 n8 (bias folded at col 27 == 1)
//   L2: H1[16,64] @ W2t -> 9 n8 (cols0..63 feat perm, col64 sigma)
//   L3: A3[16,80] @ W3t -> 8 n8 (A3 = feat ++ SH ++ 1 ++ 0, bias row73)
//   L4: H3[16,64] @ W4t -> 1 n8 (cols0..2 -> sigmoid rgb)
// ============================================================================

constexpr int TSZ = 1 << 19;

constexpr int sW1 = 56, sW2 = 72, sW3 = 88, sW4 = 72;   // elem strides [N][K]
constexpr int oW1 = 0;
constexpr int oW2 = oW1 + 64 * sW1;
constexpr int oW3 = oW2 + 72 * sW2;
constexpr int oW4 = oW3 + 64 * sW3;
constexpr int W_ELEMS = oW4 + 8 * sW4;  // 14976 elems = 29952 B

__device__ __align__(16) __half g_w[W_ELEMS];
__device__ __align__(16) float g_b2[72];
__device__ __align__(16) float g_b4[8];

constexpr int oSB2B = 29952;
constexpr int oSB4B = 30240;
constexpr int oSTB  = 30272;              // per-warp staging: 2304 B
constexpr int SMEM_DYN = oSTB + 8 * 2304; // 48704

// ---------------- PTX helpers ----------------
__device__ __forceinline__ uint32_t smem_u32(const void* p) {
    uint32_t a;
    asm("{ .reg .u64 t; cvta.to.shared.u64 t, %1; cvt.u32.u64 %0, t; }"
        : "=r"(a) : "l"(p));
    return a;
}
__device__ __forceinline__ void ldsm4(uint32_t* r, uint32_t addr) {
    asm volatile("ldmatrix.sync.aligned.m8n8.x4.shared.b16 {%0,%1,%2,%3}, [%4];"
        : "=r"(r[0]), "=r"(r[1]), "=r"(r[2]), "=r"(r[3]) : "r"(addr));
}
__device__ __forceinline__ void ldsm2(uint32_t& r0, uint32_t& r1, uint32_t addr) {
    asm volatile("ldmatrix.sync.aligned.m8n8.x2.shared.b16 {%0,%1}, [%2];"
        : "=r"(r0), "=r"(r1) : "r"(addr));
}
#define MMA4(c, a, b0_, b1_) \
    asm volatile("mma.sync.aligned.m16n8k16.row.col.f32.f16.f16.f32 " \
        "{%0,%1,%2,%3},{%4,%5,%6,%7},{%8,%9},{%0,%1,%2,%3};" \
        : "+f"((c)[0]), "+f"((c)[1]), "+f"((c)[2]), "+f"((c)[3]) \
        : "r"((a)[0]), "r"((a)[1]), "r"((a)[2]), "r"((a)[3]), "r"(b0_), "r"(b1_))

// 2 k-tiles: one ldsm4 feeds 2 MMAs
__device__ __forceinline__ void pass2(float* c, const uint32_t (*ah)[4], int kt0,
                                      uint32_t b_addr) {
    uint32_t bb[4];
    ldsm4(bb, b_addr);
    MMA4(c, ah[kt0], bb[0], bb[1]);
    MMA4(c, ah[kt0 + 1], bb[2], bb[3]);
}
// single k-tile: one ldsm2 feeds 1 MMA
__device__ __forceinline__ void pass1(float* c, const uint32_t* ah, uint32_t b_addr) {
    uint32_t r0, r1;
    ldsm2(r0, r1, b_addr);
    MMA4(c, ah, r0, r1);
}

// relu + pack fp32 pair -> fp16x2
__device__ __forceinline__ uint32_t f16r(float a, float b) {
    __half2 h = __floats2half2_rn(fmaxf(a, 0.0f), fmaxf(b, 0.0f));
    return *reinterpret_cast<uint32_t*>(&h);
}

// ---------------- weight prep ----------------
__global__ void prep_weights(const float* __restrict__ dw1, const float* __restrict__ db1,
                             const float* __restrict__ dw2, const float* __restrict__ db2,
                             const float* __restrict__ rw1, const float* __restrict__ rb1,
                             const float* __restrict__ rw2, const float* __restrict__ rb2)
{
    const int tid = threadIdx.x;
    for (int i = tid; i < W_ELEMS; i += 256) g_w[i] = __float2half_rn(0.0f);
    __syncthreads();
    // W1t[n][k]: 0..26 = dw1 rows 0..26; 27 = db1; 28..47 = dw1 rows 27..46
    for (int i = tid; i < 64 * 48; i += 256) {
        int nn = i / 48, k = i % 48;
        float w;
        if (k < 27)       w = dw1[k * 64 + nn];
        else if (k == 27) w = db1[nn];
        else              w = dw1[(k - 1) * 64 + nn];
        g_w[oW1 + nn * sW1 + k] = __float2half_rn(w);
    }
    for (int i = tid; i < 65 * 64; i += 256) {
        int nn = i / 64, k = i % 64;
        float w = (nn < 64) ? dw2[k * 65 + nn + 1] : dw2[k * 65];
        g_w[oW2 + nn * sW2 + k] = __float2half_rn(w);
    }
    for (int i = tid; i < 64 * 74; i += 256) {
        int nn = i / 74, k = i % 74;
        float w = (k < 73) ? rw1[k * 64 + nn] : rb1[nn];
        g_w[oW3 + nn * sW3 + k] = __float2half_rn(w);
    }
    for (int i = tid; i < 3 * 64; i += 256) {
        int nn = i / 64, k = i % 64;
        g_w[oW4 + nn * sW4 + k] = __float2half_rn(rw2[k * 3 + nn]);
    }
    if (tid < 72) g_b2[tid] = (tid < 64) ? db2[tid + 1] : ((tid == 64) ? db2[0] : 0.0f);
    if (tid < 8)  g_b4[tid] = (tid < 3) ? rb2[tid] : 0.0f;
}

// paired staging store: cols (c, c+1), c even
__device__ __forceinline__ void put_st2(char* H, uint32_t rbase, int c, float a, float b) {
    __half2 h = __floats2half2_rn(a, b);
    *(uint32_t*)(H + rbase + c * 2) = *reinterpret_cast<uint32_t*>(&h);
}

__device__ __forceinline__ float sigmoidf_(float z) {
    return 1.0f / (1.0f + __expf(-z));
}

// ---------------- main kernel ----------------
__global__ void __launch_bounds__(256, 2) nerf_mma5(
    const float* __restrict__ x, const float* __restrict__ v,
    const float* __restrict__ table, float* __restrict__ out, int n)
{
    extern __shared__ __align__(16) unsigned char S[];
    const int tid = threadIdx.x, wid = tid >> 5, lane = tid & 31;

    for (int i = tid; i < 29952 / 16; i += 256)
        ((uint4*)S)[i] = ((const uint4*)g_w)[i];
    float* sB2 = (float*)(S + oSB2B);
    float* sB4 = (float*)(S + oSB4B);
    if (tid < 72) sB2[tid] = g_b2[tid];
    if (tid < 8)  sB4[tid] = g_b4[tid];
    __syncthreads();

    const uint32_t uS = smem_u32(S);
    const int g = lane >> 2, t2 = (lane & 3) * 2;
    const int row = lane >> 1, half = lane & 1;

    char* stH = (char*)(S + oSTB + wid * 2304);
    const uint32_t uStH = uS + oSTB + wid * 2304;
    const uint32_t rbase = (uint32_t)row * 144;

    const uint32_t aofs   = (lane & 15) * 144 + (lane >> 4) * 16;
    const uint32_t bo112  = (lane & 7) * 112 + (lane >> 3) * 16;
    const uint32_t bo112b = (lane & 7) * 112 + ((lane >> 3) & 1) * 16;
    const uint32_t bo144  = (lane & 7) * 144 + (lane >> 3) * 16;
    const uint32_t bo176  = (lane & 7) * 176 + (lane >> 3) * 16;
    const uint32_t bo176b = (lane & 7) * 176 + ((lane >> 3) & 1) * 16;

    const uint32_t uW1  = uS + oW1 * 2 + bo112;
    const uint32_t uW1b = uS + oW1 * 2 + 64 + bo112b;
    const uint32_t uW2  = uS + oW2 * 2 + bo144;
    const uint32_t uW3  = uS + oW3 * 2 + bo176;
    const uint32_t uW3b = uS + oW3 * 2 + 128 + bo176b;
    const uint32_t uW4  = uS + oW4 * 2 + bo144;

    // one-time: zero staging cols 58..63
    if (half == 0) {
        put_st2(stH, rbase, 58, 0.0f, 0.0f);
        put_st2(stH, rbase, 60, 0.0f, 0.0f);
        put_st2(stH, rbase, 62, 0.0f, 0.0f);
    }

    const int ntiles = n >> 4;
    const int totw = gridDim.x * 8;

    for (int tile = blockIdx.x * 8 + wid; tile < ntiles; tile += totw) {
        const int p = tile * 16 + row;
        const float px0 = x[3 * p], px1 = x[3 * p + 1], px2 = x[3 * p + 2];

        // ---------------- encoding -> staging ----------------
        if (half == 0) {
            float e[28];
            e[0] = px0; e[1] = px1; e[2] = px2;
            const float pv[2] = {px0, px1};
            #pragma unroll
            for (int d = 0; d < 2; d++) {
                float fm = 1.0f;
                #pragma unroll
                for (int fr = 0; fr < 6; fr++) {
                    __sincosf(pv[d] * fm, &e[3 + d * 12 + fr], &e[9 + d * 12 + fr]);
                    fm *= 2.0f;
                }
            }
            e[27] = 1.0f;  // L1 bias column
            #pragma unroll
            for (int q = 0; q < 14; q++)
                put_st2(stH, rbase, 2 * q, e[2 * q], e[2 * q + 1]);

            const float vx = v[3 * p], vy = v[3 * p + 1], vz = v[3 * p + 2];
            put_st2(stH, rbase, 48, 0.28209479177387814f, -0.4886025119029199f * vy);
            put_st2(stH, rbase, 50,  0.4886025119029199f * vz, -0.4886025119029199f * vx);
            put_st2(stH, rbase, 52,  1.0925484305920792f * vx * vy,
                                    -1.0925484305920792f * vy * vz);
            put_st2(stH, rbase, 54,  0.9461746957575601f * vz * vz - 0.31539156525252005f,
                                    -1.0925484305920792f * vx * vz);
            put_st2(stH, rbase, 56,  0.5462742152960396f * (vx * vx - vy * vy), 1.0f);
        } else {
            float e[20];   // cols 28..47
            float fm = 1.0f;
            #pragma unroll
            for (int fr = 0; fr < 6; fr++) {
                __sincosf(px2 * fm, &e[fr], &e[6 + fr]);
                fm *= 2.0f;
            }
            const float x01x = (px0 + 1.0f) * 0.5f;
            const float x01y = (px1 + 1.0f) * 0.5f;
            const float x01z = (px2 + 1.0f) * 0.5f;
            const float resf[4] = {33.0f, 43.0f, 56.0f, 74.0f};
            #pragma unroll
            for (int lv = 0; lv < 4; lv++) {
                const float pxx = x01x * resf[lv], pyy = x01y * resf[lv], pzz = x01z * resf[lv];
                const float fx = floorf(pxx), fy = floorf(pyy), fz = floorf(pzz);
                const float tx = pxx - fx, ty = pyy - fy, tz = pzz - fz;
                const float wx = tx * tx * (3.0f - 2.0f * tx);
                const float wy = ty * ty * (3.0f - 2.0f * ty);
                const float wz = tz * tz * (3.0f - 2.0f * tz);
                const unsigned cx = (unsigned)fx, cy = (unsigned)fy, cz = (unsigned)fz;
                const float* tb = table + (size_t)lv * (TSZ * 2);
                float f0 = 0.0f, f1 = 0.0f;
                #pragma unroll
                for (int c = 0; c < 8; c++) {
                    const unsigned hx = cx + (c & 1);
                    const unsigned hy = cy + ((c >> 1) & 1);
                    const unsigned hz = cz + ((c >> 2) & 1);
                    const unsigned hsh = (hx ^ (hy * 2654435761u) ^ (hz * 805459861u)) & (unsigned)(TSZ - 1);
                    const float cw = ((c & 1) ? wx : 1.0f - wx)
                                   * (((c >> 1) & 1) ? wy : 1.0f - wy)
                                   * (((c >> 2) & 1) ? wz : 1.0f - wz);
                    const float2 tv = __ldg(reinterpret_cast<const float2*>(tb + 2u * hsh));
                    f0 = fmaf(tv.x, cw, f0);
                    f1 = fmaf(tv.y, cw, f1);
                }
                e[12 + 2 * lv] = f0;
                e[13 + 2 * lv] = f1;
            }
            #pragma unroll
            for (int q = 0; q < 10; q++)
                put_st2(stH, rbase, 28 + 2 * q, e[2 * q], e[2 * q + 1]);
        }
        __syncwarp();

        // ---------------- A1 fragments ----------------
        uint32_t a1[3][4];
        ldsm4(a1[0], uStH + aofs);
        ldsm4(a1[1], uStH + aofs + 32);
        ldsm4(a1[2], uStH + aofs + 64);

        // ---------------- L1 ----------------
        uint32_t a2[4][4];
        #pragma unroll
        for (int m = 0; m < 4; m++) {
            float c[2][4];
            #pragma unroll
            for (int u = 0; u < 2; u++) {
                const uint32_t jb = (2 * m + u) * (8 * 112);
                float* cc = c[u];
                cc[0] = cc[1] = cc[2] = cc[3] = 0.0f;
                pass2(cc, a1, 0, uW1 + jb);
                pass1(cc, a1[2], uW1b + jb);
            }
            a2[m][0] = f16r(c[0][0], c[0][1]);
            a2[m][1] = f16r(c[0][2], c[0][3]);
            a2[m][2] = f16r(c[1][0], c[1][1]);
            a2[m][3] = f16r(c[1][2], c[1][3]);
        }

        // ---------------- L2 ----------------
        uint32_t a3[5][4];
        #pragma unroll
        for (int m = 0; m < 4; m++) {
            float c[2][4];
            #pragma unroll
            for (int u = 0; u < 2; u++) {
                const int j = 2 * m + u;
                const uint32_t jb = j * (8 * 144);
                float* cc = c[u];
                const float2 bb = *(const float2*)(sB2 + 8 * j + t2);
                cc[0] = bb.x; cc[1] = bb.y; cc[2] = bb.x; cc[3] = bb.y;
                pass2(cc, a2, 0, uW2 + jb);
                pass2(cc, a2, 2, uW2 + jb + 64);
            }
            a3[m][0] = f16r(c[0][0], c[0][1]);
            a3[m][1] = f16r(c[0][2], c[0][3]);
            a3[m][2] = f16r(c[1][0], c[1][1]);
            a3[m][3] = f16r(c[1][2], c[1][3]);
        }
        {   // sigma n-tile
            float cc[4];
            const float2 bb = *(const float2*)(sB2 + 64 + t2);
            cc[0] = bb.x; cc[1] = bb.y; cc[2] = bb.x; cc[3] = bb.y;
            const uint32_t jb = 8 * (8 * 144);
            pass2(cc, a2, 0, uW2 + jb);
            pass2(cc, a2, 2, uW2 + jb + 64);
            if ((lane & 3) == 0) {
                out[tile * 16 + g]     = __expf(cc[0]);
                out[tile * 16 + g + 8] = __expf(cc[2]);
            }
        }
        ldsm4(a3[4], uStH + aofs + 96);

        // ---------------- L3 ----------------
        uint32_t a4[4][4];
        #pragma unroll
        for (int m = 0; m < 4; m++) {
            float c[2][4];
            #pragma unroll
            for (int u = 0; u < 2; u++) {
                const uint32_t jb = (2 * m + u) * (8 * 176);
                float* cc = c[u];
                cc[0] = cc[1] = cc[2] = cc[3] = 0.0f;
                pass2(cc, a3, 0, uW3 + jb);
                pass2(cc, a3, 2, uW3 + jb + 64);
                pass1(cc, a3[4], uW3b + jb);
            }
            a4[m][0] = f16r(c[0][0], c[0][1]);
            a4[m][1] = f16r(c[0][2], c[0][3]);
            a4[m][2] = f16r(c[1][0], c[1][1]);
            a4[m][3] = f16r(c[1][2], c[1][3]);
        }

        // ---------------- L4 + rgb ----------------
        {
            float cc[4];
            const float2 bb = *(const float2*)(sB4 + t2);
            cc[0] = bb.x; cc[1] = bb.y; cc[2] = bb.x; cc[3] = bb.y;
            pass2(cc, a4, 0, uW4);
            pass2(cc, a4, 2, uW4 + 64);
            const int pg = tile * 16 + g;
            if ((lane & 3) == 0) {
                out[n + 3 * pg + 0]       = sigmoidf_(cc[0]);
                out[n + 3 * pg + 1]       = sigmoidf_(cc[1]);
                out[n + 3 * (pg + 8) + 0] = sigmoidf_(cc[2]);
                out[n + 3 * (pg + 8) + 1] = sigmoidf_(cc[3]);
            } else if ((lane & 3) == 1) {
                out[n + 3 * pg + 2]       = sigmoidf_(cc[0]);
                out[n + 3 * (pg + 8) + 2] = sigmoidf_(cc[2]);
            }
        }
        __syncwarp();
    }
}

extern "C" void kernel_launch(void* const* d_in, const int* in_sizes, int n_in,
                              void* d_out, int out_size)
{
    const float* x     = (const float*)d_in[0];
    const float* v     = (const float*)d_in[1];
    const float* table = (const float*)d_in[3];
    const float* dw1   = (const float*)d_in[4];
    const float* db1   = (const float*)d_in[5];
    const float* dw2   = (const float*)d_in[6];
    const float* db2   = (const float*)d_in[7];
    const float* rw1   = (const float*)d_in[8];
    const float* rb1   = (const float*)d_in[9];
    const float* rw2   = (const float*)d_in[10];
    const float* rb2   = (const float*)d_in[11];
    float* out = (float*)d_out;

    const int n = in_sizes[0] / 3;

    cudaFuncSetAttribute(nerf_mma5, cudaFuncAttributeMaxDynamicSharedMemorySize, SMEM_DYN);

    prep_weights<<<1, 256>>>(dw1, db1, dw2, db2, rw1, rb1, rw2, rb2);
    nerf_mma5<<<296, 256, SMEM_DYN>>>(x, v, table, out, n);
}

// round 10
// speedup vs baseline: 2.0369x; 1.0356x over previous
#include <cuda_runtime.h>
#include <cuda_fp16.h>
#include <cstdint>

// ============================================================================
// GridNeRF forward: register-chained mma.sync.m16n8k16, single fp16 operands,
// M=32 per warp: two 16-row tiles share every B ldmatrix.
//   L1: A1[16,48] @ W1t -> 8 n8 (bias folded at col 27 == 1)
//   L2: H1[16,64] @ W2t -> 9 n8 (cols0..63 feat perm, col64 sigma)
//   L3: A3[16,80] @ W3t -> 8 n8 (A3 = feat ++ SH ++ 1 ++ 0, bias row73)
//   L4: H3[16,64] @ W4t -> 1 n8 (cols0..2 -> sigmoid rgb)
// ============================================================================

constexpr int TSZ = 1 << 19;

constexpr int sW1 = 56, sW2 = 72, sW3 = 88, sW4 = 72;   // elem strides [N][K]
constexpr int oW1 = 0;
constexpr int oW2 = oW1 + 64 * sW1;
constexpr int oW3 = oW2 + 72 * sW2;
constexpr int oW4 = oW3 + 64 * sW3;
constexpr int W_ELEMS = oW4 + 8 * sW4;  // 14976 elems = 29952 B

__device__ __align__(16) __half g_w[W_ELEMS];
__device__ __align__(16) float g_b2[72];
__device__ __align__(16) float g_b4[8];

constexpr int oSB2B = 29952;
constexpr int oSB4B = 30240;
constexpr int oSTB  = 30272;              // per-warp staging: 2 tiles x 2304 B
constexpr int SMEM_DYN = oSTB + 8 * 4608; // 67136

// ---------------- PTX helpers ----------------
__device__ __forceinline__ uint32_t smem_u32(const void* p) {
    uint32_t a;
    asm("{ .reg .u64 t; cvta.to.shared.u64 t, %1; cvt.u32.u64 %0, t; }"
        : "=r"(a) : "l"(p));
    return a;
}
__device__ __forceinline__ void ldsm4(uint32_t* r, uint32_t addr) {
    asm volatile("ldmatrix.sync.aligned.m8n8.x4.shared.b16 {%0,%1,%2,%3}, [%4];"
        : "=r"(r[0]), "=r"(r[1]), "=r"(r[2]), "=r"(r[3]) : "r"(addr));
}
__device__ __forceinline__ void ldsm2(uint32_t& r0, uint32_t& r1, uint32_t addr) {
    asm volatile("ldmatrix.sync.aligned.m8n8.x2.shared.b16 {%0,%1}, [%2];"
        : "=r"(r0), "=r"(r1) : "r"(addr));
}
#define MMA4(c, a, b0_, b1_) \
    asm volatile("mma.sync.aligned.m16n8k16.row.col.f32.f16.f16.f32 " \
        "{%0,%1,%2,%3},{%4,%5,%6,%7},{%8,%9},{%0,%1,%2,%3};" \
        : "+f"((c)[0]), "+f"((c)[1]), "+f"((c)[2]), "+f"((c)[3]) \
        : "r"((a)[0]), "r"((a)[1]), "r"((a)[2]), "r"((a)[3]), "r"(b0_), "r"(b1_))

// 2 k-tiles, 2 row-tiles: one ldsm4 feeds 4 MMAs
__device__ __forceinline__ void pass2d(float* c0, float* c1,
    const uint32_t (*a0)[4], const uint32_t (*a1t)[4], int k0, uint32_t b_addr)
{
    uint32_t bb[4];
    ldsm4(bb, b_addr);
    MMA4(c0, a0[k0], bb[0], bb[1]);
    MMA4(c1, a1t[k0], bb[0], bb[1]);
    MMA4(c0, a0[k0 + 1], bb[2], bb[3]);
    MMA4(c1, a1t[k0 + 1], bb[2], bb[3]);
}
// single k-tile, 2 row-tiles: one ldsm2 feeds 2 MMAs
__device__ __forceinline__ void pass1d(float* c0, float* c1,
    const uint32_t* a0, const uint32_t* a1t, uint32_t b_addr)
{
    uint32_t r0, r1;
    ldsm2(r0, r1, b_addr);
    MMA4(c0, a0, r0, r1);
    MMA4(c1, a1t, r0, r1);
}

// relu + pack fp32 pair -> fp16x2
__device__ __forceinline__ uint32_t f16r(float a, float b) {
    __half2 h = __floats2half2_rn(fmaxf(a, 0.0f), fmaxf(b, 0.0f));
    return *reinterpret_cast<uint32_t*>(&h);
}

// ---------------- weight prep ----------------
__global__ void prep_weights(const float* __restrict__ dw1, const float* __restrict__ db1,
                             const float* __restrict__ dw2, const float* __restrict__ db2,
                             const float* __restrict__ rw1, const float* __restrict__ rb1,
                             const float* __restrict__ rw2, const float* __restrict__ rb2)
{
    const int tid = threadIdx.x;
    for (int i = tid; i < W_ELEMS; i += 256) g_w[i] = __float2half_rn(0.0f);
    __syncthreads();
    for (int i = tid; i < 64 * 48; i += 256) {
        int nn = i / 48, k = i % 48;
        float w;
        if (k < 27)       w = dw1[k * 64 + nn];
        else if (k == 27) w = db1[nn];
        else              w = dw1[(k - 1) * 64 + nn];
        g_w[oW1 + nn * sW1 + k] = __float2half_rn(w);
    }
    for (int i = tid; i < 65 * 64; i += 256) {
        int nn = i / 64, k = i % 64;
        float w = (nn < 64) ? dw2[k * 65 + nn + 1] : dw2[k * 65];
        g_w[oW2 + nn * sW2 + k] = __float2half_rn(w);
    }
    for (int i = tid; i < 64 * 74; i += 256) {
        int nn = i / 74, k = i % 74;
        float w = (k < 73) ? rw1[k * 64 + nn] : rb1[nn];
        g_w[oW3 + nn * sW3 + k] = __float2half_rn(w);
    }
    for (int i = tid; i < 3 * 64; i += 256) {
        int nn = i / 64, k = i % 64;
        g_w[oW4 + nn * sW4 + k] = __float2half_rn(rw2[k * 3 + nn]);
    }
    if (tid < 72) g_b2[tid] = (tid < 64) ? db2[tid + 1] : ((tid == 64) ? db2[0] : 0.0f);
    if (tid < 8)  g_b4[tid] = (tid < 3) ? rb2[tid] : 0.0f;
}

__device__ __forceinline__ void put_st2(char* H, uint32_t rbase, int c, float a, float b) {
    __half2 h = __floats2half2_rn(a, b);
    *(uint32_t*)(H + rbase + c * 2) = *reinterpret_cast<uint32_t*>(&h);
}

__device__ __forceinline__ void encode_tile(
    char* stH, uint32_t rbase, int row, int half, int p,
    const float* __restrict__ x, const float* __restrict__ v,
    const float* __restrict__ table)
{
    const float px0 = x[3 * p], px1 = x[3 * p + 1], px2 = x[3 * p + 2];
    if (half == 0) {
        float e[28];
        e[0] = px0; e[1] = px1; e[2] = px2;
        const float pv[2] = {px0, px1};
        #pragma unroll
        for (int d = 0; d < 2; d++) {
            float fm = 1.0f;
            #pragma unroll
            for (int fr = 0; fr < 6; fr++) {
                __sincosf(pv[d] * fm, &e[3 + d * 12 + fr], &e[9 + d * 12 + fr]);
                fm *= 2.0f;
            }
        }
        e[27] = 1.0f;  // L1 bias column
        #pragma unroll
        for (int q = 0; q < 14; q++)
            put_st2(stH, rbase, 2 * q, e[2 * q], e[2 * q + 1]);

        const float vx = v[3 * p], vy = v[3 * p + 1], vz = v[3 * p + 2];
        put_st2(stH, rbase, 48, 0.28209479177387814f, -0.4886025119029199f * vy);
        put_st2(stH, rbase, 50,  0.4886025119029199f * vz, -0.4886025119029199f * vx);
        put_st2(stH, rbase, 52,  1.0925484305920792f * vx * vy,
                                -1.0925484305920792f * vy * vz);
        put_st2(stH, rbase, 54,  0.9461746957575601f * vz * vz - 0.31539156525252005f,
                                -1.0925484305920792f * vx * vz);
        put_st2(stH, rbase, 56,  0.5462742152960396f * (vx * vx - vy * vy), 1.0f);
    } else {
        float e[20];   // cols 28..47
        float fm = 1.0f;
        #pragma unroll
        for (int fr = 0; fr < 6; fr++) {
            __sincosf(px2 * fm, &e[fr], &e[6 + fr]);
            fm *= 2.0f;
        }
        const float x01x = (px0 + 1.0f) * 0.5f;
        const float x01y = (px1 + 1.0f) * 0.5f;
        const float x01z = (px2 + 1.0f) * 0.5f;
        const float resf[4] = {33.0f, 43.0f, 56.0f, 74.0f};
        #pragma unroll
        for (int lv = 0; lv < 4; lv++) {
            const float pxx = x01x * resf[lv], pyy = x01y * resf[lv], pzz = x01z * resf[lv];
            const float fx = floorf(pxx), fy = floorf(pyy), fz = floorf(pzz);
            const float tx = pxx - fx, ty = pyy - fy, tz = pzz - fz;
            const float wx = tx * tx * (3.0f - 2.0f * tx);
            const float wy = ty * ty * (3.0f - 2.0f * ty);
            const float wz = tz * tz * (3.0f - 2.0f * tz);
            const unsigned cx = (unsigned)fx, cy = (unsigned)fy, cz = (unsigned)fz;
            const float* tb = table + (size_t)lv * (TSZ * 2);
            float f0 = 0.0f, f1 = 0.0f;
            #pragma unroll
            for (int c = 0; c < 8; c++) {
                const unsigned hx = cx + (c & 1);
                const unsigned hy = cy + ((c >> 1) & 1);
                const unsigned hz = cz + ((c >> 2) & 1);
                const unsigned hsh = (hx ^ (hy * 2654435761u) ^ (hz * 805459861u)) & (unsigned)(TSZ - 1);
                const float cw = ((c & 1) ? wx : 1.0f - wx)
                               * (((c >> 1) & 1) ? wy : 1.0f - wy)
                               * (((c >> 2) & 1) ? wz : 1.0f - wz);
                const float2 tv = __ldg(reinterpret_cast<const float2*>(tb + 2u * hsh));
                f0 = fmaf(tv.x, cw, f0);
                f1 = fmaf(tv.y, cw, f1);
            }
            e[12 + 2 * lv] = f0;
            e[13 + 2 * lv] = f1;
        }
        #pragma unroll
        for (int q = 0; q < 10; q++)
            put_st2(stH, rbase, 28 + 2 * q, e[2 * q], e[2 * q + 1]);
    }
}

__device__ __forceinline__ float sigmoidf_(float z) {
    return 1.0f / (1.0f + __expf(-z));
}

// ---------------- main kernel ----------------
__global__ void __launch_bounds__(256, 2) nerf_mma6(
    const float* __restrict__ x, const float* __restrict__ v,
    const float* __restrict__ table, float* __restrict__ out, int n)
{
    extern __shared__ __align__(16) unsigned char S[];
    const int tid = threadIdx.x, wid = tid >> 5, lane = tid & 31;

    for (int i = tid; i < 29952 / 16; i += 256)
        ((uint4*)S)[i] = ((const uint4*)g_w)[i];
    float* sB2 = (float*)(S + oSB2B);
    float* sB4 = (float*)(S + oSB4B);
    if (tid < 72) sB2[tid] = g_b2[tid];
    if (tid < 8)  sB4[tid] = g_b4[tid];
    __syncthreads();

    const uint32_t uS = smem_u32(S);
    const int g = lane >> 2, t2 = (lane & 3) * 2;
    const int row = lane >> 1, half = lane & 1;

    char* st0 = (char*)(S + oSTB + wid * 4608);
    char* st1 = st0 + 2304;
    const uint32_t uSt0 = uS + oSTB + wid * 4608;
    const uint32_t uSt1 = uSt0 + 2304;
    const uint32_t rbase = (uint32_t)row * 144;

    const uint32_t aofs   = (lane & 15) * 144 + (lane >> 4) * 16;
    const uint32_t bo112  = (lane & 7) * 112 + (lane >> 3) * 16;
    const uint32_t bo112b = (lane & 7) * 112 + ((lane >> 3) & 1) * 16;
    const uint32_t bo144  = (lane & 7) * 144 + (lane >> 3) * 16;
    const uint32_t bo176  = (lane & 7) * 176 + (lane >> 3) * 16;
    const uint32_t bo176b = (lane & 7) * 176 + ((lane >> 3) & 1) * 16;

    const uint32_t uW1  = uS + oW1 * 2 + bo112;
    const uint32_t uW1b = uS + oW1 * 2 + 64 + bo112b;
    const uint32_t uW2  = uS + oW2 * 2 + bo144;
    const uint32_t uW3  = uS + oW3 * 2 + bo176;
    const uint32_t uW3b = uS + oW3 * 2 + 128 + bo176b;
    const uint32_t uW4  = uS + oW4 * 2 + bo144;

    // one-time: zero staging cols 58..63 of both tiles
    if (half == 0) {
        put_st2(st0, rbase, 58, 0.0f, 0.0f);
        put_st2(st0, rbase, 60, 0.0f, 0.0f);
        put_st2(st0, rbase, 62, 0.0f, 0.0f);
        put_st2(st1, rbase, 58, 0.0f, 0.0f);
        put_st2(st1, rbase, 60, 0.0f, 0.0f);
        put_st2(st1, rbase, 62, 0.0f, 0.0f);
    }

    const int npairs = n >> 5;
    const int totw = gridDim.x * 8;

    for (int pair = blockIdx.x * 8 + wid; pair < npairs; pair += totw) {
        const int t0 = 2 * pair, t1 = 2 * pair + 1;

        encode_tile(st0, rbase, row, half, t0 * 16 + row, x, v, table);
        encode_tile(st1, rbase, row, half, t1 * 16 + row, x, v, table);
        __syncwarp();

        // ---------------- A1 fragments ----------------
        uint32_t a1[2][3][4];
        #pragma unroll
        for (int k = 0; k < 3; k++) {
            ldsm4(a1[0][k], uSt0 + aofs + 32 * k);
            ldsm4(a1[1][k], uSt1 + aofs + 32 * k);
        }

        // ---------------- L1 ----------------
        uint32_t a2[2][4][4];
        #pragma unroll
        for (int m = 0; m < 4; m++) {
            float c[2][2][4];   // [u][tile]
            #pragma unroll
            for (int u = 0; u < 2; u++) {
                const uint32_t jb = (2 * m + u) * (8 * 112);
                float *c0 = c[u][0], *c1 = c[u][1];
                #pragma unroll
                for (int q = 0; q < 4; q++) { c0[q] = 0.0f; c1[q] = 0.0f; }
                pass2d(c0, c1, a1[0], a1[1], 0, uW1 + jb);
                pass1d(c0, c1, a1[0][2], a1[1][2], uW1b + jb);
            }
            #pragma unroll
            for (int tt = 0; tt < 2; tt++) {
                a2[tt][m][0] = f16r(c[0][tt][0], c[0][tt][1]);
                a2[tt][m][1] = f16r(c[0][tt][2], c[0][tt][3]);
                a2[tt][m][2] = f16r(c[1][tt][0], c[1][tt][1]);
                a2[tt][m][3] = f16r(c[1][tt][2], c[1][tt][3]);
            }
        }

        // ---------------- L2 ----------------
        uint32_t a3[2][5][4];
        #pragma unroll
        for (int m = 0; m < 4; m++) {
            float c[2][2][4];
            #pragma unroll
            for (int u = 0; u < 2; u++) {
                const int j = 2 * m + u;
                const uint32_t jb = j * (8 * 144);
                float *c0 = c[u][0], *c1 = c[u][1];
                const float2 bb = *(const float2*)(sB2 + 8 * j + t2);
                c0[0] = bb.x; c0[1] = bb.y; c0[2] = bb.x; c0[3] = bb.y;
                c1[0] = bb.x; c1[1] = bb.y; c1[2] = bb.x; c1[3] = bb.y;
                pass2d(c0, c1, a2[0], a2[1], 0, uW2 + jb);
                pass2d(c0, c1, a2[0], a2[1], 2, uW2 + jb + 64);
            }
            #pragma unroll
            for (int tt = 0; tt < 2; tt++) {
                a3[tt][m][0] = f16r(c[0][tt][0], c[0][tt][1]);
                a3[tt][m][1] = f16r(c[0][tt][2], c[0][tt][3]);
                a3[tt][m][2] = f16r(c[1][tt][0], c[1][tt][1]);
                a3[tt][m][3] = f16r(c[1][tt][2], c[1][tt][3]);
            }
        }
        {   // sigma n-tile
            float c0[4], c1[4];
            const float2 bb = *(const float2*)(sB2 + 64 + t2);
            c0[0] = bb.x; c0[1] = bb.y; c0[2] = bb.x; c0[3] = bb.y;
            c1[0] = bb.x; c1[1] = bb.y; c1[2] = bb.x; c1[3] = bb.y;
            const uint32_t jb = 8 * (8 * 144);
            pass2d(c0, c1, a2[0], a2[1], 0, uW2 + jb);
            pass2d(c0, c1, a2[0], a2[1], 2, uW2 + jb + 64);
            if ((lane & 3) == 0) {
                out[t0 * 16 + g]     = __expf(c0[0]);
                out[t0 * 16 + g + 8] = __expf(c0[2]);
                out[t1 * 16 + g]     = __expf(c1[0]);
                out[t1 * 16 + g + 8] = __expf(c1[2]);
            }
        }
        ldsm4(a3[0][4], uSt0 + aofs + 96);
        ldsm4(a3[1][4], uSt1 + aofs + 96);

        // ---------------- L3 ----------------
        uint32_t a4[2][4][4];
        #pragma unroll
        for (int m = 0; m < 4; m++) {
            float c[2][2][4];
            #pragma unroll
            for (int u = 0; u < 2; u++) {
                const uint32_t jb = (2 * m + u) * (8 * 176);
                float *c0 = c[u][0], *c1 = c[u][1];
                #pragma unroll
                for (int q = 0; q < 4; q++) { c0[q] = 0.0f; c1[q] = 0.0f; }
                pass2d(c0, c1, a3[0], a3[1], 0, uW3 + jb);
                pass2d(c0, c1, a3[0], a3[1], 2, uW3 + jb + 64);
                pass1d(c0, c1, a3[0][4], a3[1][4], uW3b + jb);
            }
            #pragma unroll
            for (int tt = 0; tt < 2; tt++) {
                a4[tt][m][0] = f16r(c[0][tt][0], c[0][tt][1]);
                a4[tt][m][1] = f16r(c[0][tt][2], c[0][tt][3]);
                a4[tt][m][2] = f16r(c[1][tt][0], c[1][tt][1]);
                a4[tt][m][3] = f16r(c[1][tt][2], c[1][tt][3]);
            }
        }

        // ---------------- L4 + rgb ----------------
        {
            float c0[4], c1[4];
            const float2 bb = *(const float2*)(sB4 + t2);
            c0[0] = bb.x; c0[1] = bb.y; c0[2] = bb.x; c0[3] = bb.y;
            c1[0] = bb.x; c1[1] = bb.y; c1[2] = bb.x; c1[3] = bb.y;
            pass2d(c0, c1, a4[0], a4[1], 0, uW4);
            pass2d(c0, c1, a4[0], a4[1], 2, uW4 + 64);
            const int p0 = t0 * 16 + g, p1 = t1 * 16 + g;
            if ((lane & 3) == 0) {
                out[n + 3 * p0 + 0]       = sigmoidf_(c0[0]);
                out[n + 3 * p0 + 1]       = sigmoidf_(c0[1]);
                out[n + 3 * (p0 + 8) + 0] = sigmoidf_(c0[2]);
                out[n + 3 * (p0 + 8) + 1] = sigmoidf_(c0[3]);
                out[n + 3 * p1 + 0]       = sigmoidf_(c1[0]);
                out[n + 3 * p1 + 1]       = sigmoidf_(c1[1]);
                out[n + 3 * (p1 + 8) + 0] = sigmoidf_(c1[2]);
                out[n + 3 * (p1 + 8) + 1] = sigmoidf_(c1[3]);
            } else if ((lane & 3) == 1) {
                out[n + 3 * p0 + 2]       = sigmoidf_(c0[0]);
                out[n + 3 * (p0 + 8) + 2] = sigmoidf_(c0[2]);
                out[n + 3 * p1 + 2]       = sigmoidf_(c1[0]);
                out[n + 3 * (p1 + 8) + 2] = sigmoidf_(c1[2]);
            }
        }
        __syncwarp();
    }
}

extern "C" void kernel_launch(void* const* d_in, const int* in_sizes, int n_in,
                              void* d_out, int out_size)
{
    const float* x     = (const float*)d_in[0];
    const float* v     = (const float*)d_in[1];
    const float* table = (const float*)d_in[3];
    const float* dw1   = (const float*)d_in[4];
    const float* db1   = (const float*)d_in[5];
    const float* dw2   = (const float*)d_in[6];
    const float* db2   = (const float*)d_in[7];
    const float* rw1   = (const float*)d_in[8];
    const float* rb1   = (const float*)d_in[9];
    const float* rw2   = (const float*)d_in[10];
    const float* rb2   = (const float*)d_in[11];
    float* out = (float*)d_out;

    const int n = in_sizes[0] / 3;

    cudaFuncSetAttribute(nerf_mma6, cudaFuncAttributeMaxDynamicSharedMemorySize, SMEM_DYN);

    prep_weights<<<1, 256>>>(dw1, db1, dw2, db2, rw1, rb1, rw2, rb2);
    nerf_mma6<<<296, 256, SMEM_DYN>>>(x, v, table, out, n);
}